// round 10
// baseline (speedup 1.0000x reference)
#include <cuda_runtime.h>
#include <cuda_bf16.h>
#include <math.h>

// Problem constants
#define BB    4
#define CC    256
#define HH    256
#define WW    256
#define HWSZ  (HH * WW)
#define NROI  2048
#define FEAT  2304          // 9 * 256
#define DD    256

// Weight-plane offsets (elements) into g_wH / g_wL
#define OFF_SH1   0
#define OFF_SH2   589824
#define OFF_CLS1  655360
#define OFF_CLS2  720896
#define OFF_IOU1  786432
#define OFF_IOU2  851968
#define OFF_REG1  917504
#define OFF_REG2  983040
#define WTOT      1048576

// Scratch (device globals; no allocation allowed)
__device__ float          g_fmT[(size_t)BB * HWSZ * CC];     // [B,H,W,C]
__device__ __nv_bfloat16  g_xH[(size_t)NROI * FEAT];
__device__ __nv_bfloat16  g_xL[(size_t)NROI * FEAT];
__device__ __nv_bfloat16  g_wH[WTOT];
__device__ __nv_bfloat16  g_wL[WTOT];
__device__ float          g_part1[(size_t)4 * NROI * DD];    // sh1 split-K partials
__device__ __nv_bfloat16  g_aH[(size_t)NROI * DD];
__device__ __nv_bfloat16  g_aL[(size_t)NROI * DD];
__device__ __nv_bfloat16  g_shH[(size_t)NROI * DD];
__device__ __nv_bfloat16  g_shL[(size_t)NROI * DD];
__device__ __nv_bfloat16  g_l1H[(size_t)3 * NROI * DD];
__device__ __nv_bfloat16  g_l1L[(size_t)3 * NROI * DD];
__device__ float          g_bufL2[(size_t)3 * NROI * DD];

// ---------------------------------------------------------------------------
// K0: transpose one batch [C,H,W] -> [H,W,C]  (per-batch for L2 residency)
// ---------------------------------------------------------------------------
__global__ __launch_bounds__(256) void transpose_kernel(const float* __restrict__ fm,
                                                        int b) {
    __shared__ float tile[32][33];
    int hw0 = blockIdx.x * 32;
    int c0  = blockIdx.y * 32;
    int tx = threadIdx.x, ty = threadIdx.y;      // 32 x 8
    const float* src = fm + (size_t)b * CC * HWSZ;
    #pragma unroll
    for (int k = 0; k < 4; k++) {
        int c = c0 + ty + 8 * k;
        tile[ty + 8 * k][tx] = src[(size_t)c * HWSZ + hw0 + tx];
    }
    __syncthreads();
    float* dst = g_fmT + (size_t)b * HWSZ * CC;
    #pragma unroll
    for (int k = 0; k < 4; k++) {
        int hw = hw0 + ty + 8 * k;
        dst[(size_t)hw * CC + c0 + tx] = tile[tx][ty + 8 * k];
    }
}

// ---------------------------------------------------------------------------
// K1: rotated ROI align for rois of batch `bsel` -> bf16 hi/lo features
// ---------------------------------------------------------------------------
__global__ __launch_bounds__(256) void roi_kernel(const float* __restrict__ boxes,
                                                  const int* __restrict__ bidx,
                                                  int bsel) {
    int n = blockIdx.x;
    int b = bidx[n];
    if (b != bsel) return;
    int c = threadIdx.x;   // channel

    __shared__ int   s_i00[36], s_i01[36], s_i10[36], s_i11[36];
    __shared__ float s_w[36][4];

    if (c < 36) {
        int s  = c;
        int ix = s & 1;
        int iy = (s >> 1) & 1;
        int p  = s >> 2;
        int pw = p % 3;
        int ph = p / 3;

        float b0 = boxes[n * 7 + 0];
        float b1 = boxes[n * 7 + 1];
        float b4 = boxes[n * 7 + 4];
        float b5 = boxes[n * 7 + 5];
        float b6 = boxes[n * 7 + 6];

        const float gw = 102.4f / 256.0f;
        float cx = (b0 + 51.2f) / gw - 0.5f;
        float cy = (b1 + 51.2f) / gw - 0.5f;
        float rw = b5 / gw;
        float rh = b4 / gw;
        float theta = -b6;
        float ct = cosf(theta), st = sinf(theta);
        float bin_h = rh / 3.0f, bin_w = rw / 3.0f;

        float sgy = ((float)iy + 0.5f) * 0.5f;
        float sgx = ((float)ix + 0.5f) * 0.5f;
        float yy = -rh * 0.5f + ((float)ph + sgy) * bin_h;
        float xx = -rw * 0.5f + ((float)pw + sgx) * bin_w;
        float y = yy * ct - xx * st + cy;
        float x = yy * st + xx * ct + cx;

        bool valid = (y > -1.0f) && (y < (float)HH) && (x > -1.0f) && (x < (float)WW);
        y = fminf(fmaxf(y, 0.0f), (float)(HH - 1));
        x = fminf(fmaxf(x, 0.0f), (float)(WW - 1));
        int y0 = min((int)floorf(y), HH - 1);
        int x0 = min((int)floorf(x), WW - 1);
        int y1 = min(y0 + 1, HH - 1);
        int x1 = min(x0 + 1, WW - 1);
        float ly = y - (float)y0, lx = x - (float)x0;
        float hy = 1.0f - ly, hx = 1.0f - lx;
        float v = valid ? 1.0f : 0.0f;

        s_i00[s] = y0 * WW + x0;
        s_i01[s] = y0 * WW + x1;
        s_i10[s] = y1 * WW + x0;
        s_i11[s] = y1 * WW + x1;
        s_w[s][0] = hy * hx * v;
        s_w[s][1] = hy * lx * v;
        s_w[s][2] = ly * hx * v;
        s_w[s][3] = ly * lx * v;
    }
    __syncthreads();

    const float* base = g_fmT + (size_t)b * HWSZ * CC + c;

    float acc[9];
    #pragma unroll
    for (int p = 0; p < 9; p++) acc[p] = 0.0f;

    #pragma unroll
    for (int s = 0; s < 36; s++) {
        float v = s_w[s][0] * base[(size_t)s_i00[s] * CC]
                + s_w[s][1] * base[(size_t)s_i01[s] * CC]
                + s_w[s][2] * base[(size_t)s_i10[s] * CC]
                + s_w[s][3] * base[(size_t)s_i11[s] * CC];
        acc[s >> 2] += v;
    }

    size_t o = (size_t)n * FEAT + c;
    #pragma unroll
    for (int p = 0; p < 9; p++) {
        float val = acc[p] * 0.25f;
        __nv_bfloat16 h = __float2bfloat16(val);
        __nv_bfloat16 l = __float2bfloat16(val - __bfloat162float(h));
        g_xH[o + (size_t)p * CC] = h;
        g_xL[o + (size_t)p * CC] = l;
    }
}

// ---------------------------------------------------------------------------
// K1b: convert all GEMM weights to bf16 hi/lo planes (flat, float4 per thread)
// ---------------------------------------------------------------------------
__global__ __launch_bounds__(256) void wconv_kernel(
    const float* __restrict__ w_sh1, const float* __restrict__ w_sh2,
    const float* __restrict__ w_cls1, const float* __restrict__ w_cls2,
    const float* __restrict__ w_iou1, const float* __restrict__ w_iou2,
    const float* __restrict__ w_reg1, const float* __restrict__ w_reg2)
{
    int i4 = blockIdx.x * blockDim.x + threadIdx.x;
    if (i4 >= WTOT / 4) return;
    int idx = i4 * 4;

    const float* src;
    int loc;
    if      (idx < OFF_SH2)  { src = w_sh1;  loc = idx - OFF_SH1;  }
    else if (idx < OFF_CLS1) { src = w_sh2;  loc = idx - OFF_SH2;  }
    else if (idx < OFF_CLS2) { src = w_cls1; loc = idx - OFF_CLS1; }
    else if (idx < OFF_IOU1) { src = w_cls2; loc = idx - OFF_CLS2; }
    else if (idx < OFF_IOU2) { src = w_iou1; loc = idx - OFF_IOU1; }
    else if (idx < OFF_REG1) { src = w_iou2; loc = idx - OFF_IOU2; }
    else if (idx < OFF_REG2) { src = w_reg1; loc = idx - OFF_REG1; }
    else                     { src = w_reg2; loc = idx - OFF_REG2; }

    float4 v = *(const float4*)(src + loc);
    __nv_bfloat162 h0 = __floats2bfloat162_rn(v.x, v.y);
    __nv_bfloat162 l0 = __floats2bfloat162_rn(v.x - __low2float(h0), v.y - __high2float(h0));
    __nv_bfloat162 h1 = __floats2bfloat162_rn(v.z, v.w);
    __nv_bfloat162 l1 = __floats2bfloat162_rn(v.z - __low2float(h1), v.w - __high2float(h1));
    ((uint2*)g_wH)[i4] = make_uint2(*(unsigned*)&h0, *(unsigned*)&h1);
    ((uint2*)g_wL)[i4] = make_uint2(*(unsigned*)&l0, *(unsigned*)&l1);
}

// ---------------------------------------------------------------------------
// K2: 3xBF16 tensor-core GEMM, pre-converted bf16 hi/lo operands.
// C = [relu](A @ W^T);  D += aH*wH + aL*wH + aH*wL.
// CTA tile 64x64, 128 threads (4 warps of 32x32), k-step 16 (m16n8k16.bf16).
// smem: [64 rows][12 words]; word = bf16x2. Swizzle kw ^ 4*bit3(row).
//
//  kSplit=1: blockIdx.z picks k-chunk; out -> partial buffer z.
//  kSplit=0: blockIdx.z picks branch weight offset off0/1/2; A offset aZstride*z.
//  outMode: 0 = fp32 raw, 1 = fp32 relu, 2 = bf16 hi/lo relu
// ---------------------------------------------------------------------------
__device__ __forceinline__ void mma16(float* c, const unsigned* a, const unsigned* b) {
    asm volatile(
        "mma.sync.aligned.m16n8k16.row.col.f32.bf16.bf16.f32 "
        "{%0,%1,%2,%3}, {%4,%5,%6,%7}, {%8,%9}, {%0,%1,%2,%3};\n"
        : "+f"(c[0]), "+f"(c[1]), "+f"(c[2]), "+f"(c[3])
        : "r"(a[0]), "r"(a[1]), "r"(a[2]), "r"(a[3]), "r"(b[0]), "r"(b[1]));
}

__global__ __launch_bounds__(128) void gemm_bf16hl_kernel(
    const __nv_bfloat16* __restrict__ AH, const __nv_bfloat16* __restrict__ AL,
    size_t aZstride, int Krow, int Kchunk, int kSplit,
    size_t off0, size_t off1, size_t off2,
    float* __restrict__ Cf, unsigned* __restrict__ CH, unsigned* __restrict__ CL,
    size_t cZstride, int outMode)
{
    __shared__ unsigned AsH[64][12], AsL[64][12];
    __shared__ unsigned BsH[64][12], BsL[64][12];

    int z = blockIdx.z;
    size_t woff = kSplit ? off0 : ((z == 0) ? off0 : (z == 1) ? off1 : off2);
    int kBase = kSplit ? z * Kchunk : 0;
    size_t aoff = kSplit ? 0 : aZstride * (size_t)z;

    int row0 = blockIdx.y * 64, col0 = blockIdx.x * 64;
    int tid  = threadIdx.x;
    int warp = tid >> 5, lane = tid & 31;
    int g = lane >> 2, tg = lane & 3;
    int wm = (warp >> 1) * 32, wn = (warp & 1) * 32;

    int lr = tid >> 1;                              // 0..63 (smem row)
    int lq = (tid & 1) * 8;                         // k offset 0 or 8
    int sbase = (lq >> 1) ^ (((lr >> 3) & 1) << 2); // swizzled word base

    size_t abase = aoff + (size_t)(row0 + lr) * Krow + kBase + lq;
    size_t wbase = woff + (size_t)(col0 + lr) * Krow + kBase + lq;

    uint4 pa_h = *(const uint4*)(AH + abase);
    uint4 pa_l = *(const uint4*)(AL + abase);
    uint4 pw_h = *(const uint4*)(g_wH + wbase);
    uint4 pw_l = *(const uint4*)(g_wL + wbase);

    float acc[2][4][4];
    #pragma unroll
    for (int i = 0; i < 2; i++)
        #pragma unroll
        for (int j = 0; j < 4; j++)
            #pragma unroll
            for (int k = 0; k < 4; k++) acc[i][j][k] = 0.0f;

    for (int k0 = 0; k0 < Kchunk; k0 += 16) {
        __syncthreads();
        *(uint4*)&AsH[lr][sbase] = pa_h;
        *(uint4*)&AsL[lr][sbase] = pa_l;
        *(uint4*)&BsH[lr][sbase] = pw_h;
        *(uint4*)&BsL[lr][sbase] = pw_l;
        __syncthreads();

        if (k0 + 16 < Kchunk) {
            pa_h = *(const uint4*)(AH + abase + k0 + 16);
            pa_l = *(const uint4*)(AL + abase + k0 + 16);
            pw_h = *(const uint4*)(g_wH + wbase + k0 + 16);
            pw_l = *(const uint4*)(g_wL + wbase + k0 + 16);
        }

        unsigned aH[2][4], aL[2][4], bHf[4][2], bLf[4][2];
        #pragma unroll
        for (int mt = 0; mt < 2; mt++) {
            int r = wm + mt * 16 + g;        // bit3(r) = 0
            aH[mt][0] = AsH[r][tg];
            aH[mt][1] = AsH[r + 8][tg + 4];  // swizzled
            aH[mt][2] = AsH[r][tg + 4];
            aH[mt][3] = AsH[r + 8][tg];
            aL[mt][0] = AsL[r][tg];
            aL[mt][1] = AsL[r + 8][tg + 4];
            aL[mt][2] = AsL[r][tg + 4];
            aL[mt][3] = AsL[r + 8][tg];
        }
        #pragma unroll
        for (int nt = 0; nt < 4; nt++) {
            int nn = wn + nt * 8 + g;
            int s = (nt & 1) << 2;           // bit3(n) = nt&1
            bHf[nt][0] = BsH[nn][tg ^ s];
            bHf[nt][1] = BsH[nn][(tg + 4) ^ s];
            bLf[nt][0] = BsL[nn][tg ^ s];
            bLf[nt][1] = BsL[nn][(tg + 4) ^ s];
        }
        #pragma unroll
        for (int mt = 0; mt < 2; mt++)
            #pragma unroll
            for (int nt = 0; nt < 4; nt++) {
                mma16(acc[mt][nt], aH[mt], bHf[nt]);
                mma16(acc[mt][nt], aL[mt], bHf[nt]);
                mma16(acc[mt][nt], aH[mt], bLf[nt]);
            }
    }

    #pragma unroll
    for (int mt = 0; mt < 2; mt++) {
        int r = row0 + wm + mt * 16 + g;
        #pragma unroll
        for (int nt = 0; nt < 4; nt++) {
            int cb = col0 + wn + nt * 8 + 2 * tg;
            float v0 = acc[mt][nt][0], v1 = acc[mt][nt][1];
            float v2 = acc[mt][nt][2], v3 = acc[mt][nt][3];
            if (outMode >= 1) {
                v0 = fmaxf(v0, 0.0f); v1 = fmaxf(v1, 0.0f);
                v2 = fmaxf(v2, 0.0f); v3 = fmaxf(v3, 0.0f);
            }
            size_t i0 = cZstride * (size_t)z + (size_t)r * DD + cb;
            size_t i1 = cZstride * (size_t)z + (size_t)(r + 8) * DD + cb;
            if (outMode == 2) {
                __nv_bfloat162 h0 = __floats2bfloat162_rn(v0, v1);
                __nv_bfloat162 l0 = __floats2bfloat162_rn(v0 - __low2float(h0),
                                                          v1 - __high2float(h0));
                __nv_bfloat162 h1 = __floats2bfloat162_rn(v2, v3);
                __nv_bfloat162 l1 = __floats2bfloat162_rn(v2 - __low2float(h1),
                                                          v3 - __high2float(h1));
                CH[i0 >> 1] = *(unsigned*)&h0;
                CL[i0 >> 1] = *(unsigned*)&l0;
                CH[i1 >> 1] = *(unsigned*)&h1;
                CL[i1 >> 1] = *(unsigned*)&l1;
            } else {
                *(float2*)&Cf[i0] = make_float2(v0, v1);
                *(float2*)&Cf[i1] = make_float2(v2, v3);
            }
        }
    }
}

// ---------------------------------------------------------------------------
// K2b: reduce 4 split-K partials + relu -> bf16 hi/lo
// ---------------------------------------------------------------------------
__global__ __launch_bounds__(256) void reduce4_relu_kernel(
    const float* __restrict__ p, int n4)
{
    int i = blockIdx.x * blockDim.x + threadIdx.x;
    if (i >= n4) return;
    const float4* p4 = (const float4*)p;
    float4 a = p4[i];
    float4 b = p4[i + n4];
    float4 c = p4[i + 2 * n4];
    float4 d = p4[i + 3 * n4];
    float x = fmaxf(a.x + b.x + c.x + d.x, 0.0f);
    float y = fmaxf(a.y + b.y + c.y + d.y, 0.0f);
    float z = fmaxf(a.z + b.z + c.z + d.z, 0.0f);
    float w = fmaxf(a.w + b.w + c.w + d.w, 0.0f);
    __nv_bfloat162 h0 = __floats2bfloat162_rn(x, y);
    __nv_bfloat162 l0 = __floats2bfloat162_rn(x - __low2float(h0), y - __high2float(h0));
    __nv_bfloat162 h1 = __floats2bfloat162_rn(z, w);
    __nv_bfloat162 l1 = __floats2bfloat162_rn(z - __low2float(h1), w - __high2float(h1));
    ((uint2*)g_aH)[i] = make_uint2(*(unsigned*)&h0, *(unsigned*)&h1);
    ((uint2*)g_aL)[i] = make_uint2(*(unsigned*)&l0, *(unsigned*)&l1);
}

// ---------------------------------------------------------------------------
// K3: all three heads in one launch. Warp per (branch, row).
// ---------------------------------------------------------------------------
__global__ __launch_bounds__(256) void head_all_kernel(
    const float* __restrict__ Abase,
    const float* __restrict__ w_cls3, const float* __restrict__ b_cls3,
    const float* __restrict__ w_iou3, const float* __restrict__ b_iou3,
    const float* __restrict__ w_reg3, const float* __restrict__ b_reg3,
    float* __restrict__ out, int N)
{
    int gw   = (int)((blockIdx.x * blockDim.x + threadIdx.x) >> 5);
    int lane = threadIdx.x & 31;
    if (gw >= 3 * N) return;
    int br = gw / N, n = gw % N;

    const float* a = Abase + (size_t)br * N * DD + (size_t)n * DD;
    float av[8];
    #pragma unroll
    for (int i = 0; i < 8; i++) av[i] = a[lane + 32 * i];

    const float* Wm = (br == 0) ? w_cls3 : (br == 1) ? w_iou3 : w_reg3;
    const float* bs = (br == 0) ? b_cls3 : (br == 1) ? b_iou3 : b_reg3;
    int Dout = (br == 2) ? 7 : 1;
    float* o = out + ((br == 0) ? n : (br == 1) ? (N + n) : (2 * N + n * 7));

    for (int d = 0; d < Dout; d++) {
        const float* w = Wm + (size_t)d * DD;
        float s = 0.0f;
        #pragma unroll
        for (int i = 0; i < 8; i++) s = fmaf(av[i], w[lane + 32 * i], s);
        #pragma unroll
        for (int off = 16; off > 0; off >>= 1)
            s += __shfl_xor_sync(0xffffffffu, s, off);
        if (lane == 0) o[d] = s + bs[d];
    }
}

// ---------------------------------------------------------------------------
extern "C" void kernel_launch(void* const* d_in, const int* in_sizes, int n_in,
                              void* d_out, int out_size) {
    const float* fm     = (const float*)d_in[0];
    const float* boxes  = (const float*)d_in[1];
    const int*   bidx   = (const int*)  d_in[2];
    const float* w_sh1  = (const float*)d_in[3];
    const float* w_sh2  = (const float*)d_in[4];
    const float* w_cls1 = (const float*)d_in[5];
    const float* w_cls2 = (const float*)d_in[6];
    const float* w_cls3 = (const float*)d_in[7];
    const float* b_cls3 = (const float*)d_in[8];
    const float* w_iou1 = (const float*)d_in[9];
    const float* w_iou2 = (const float*)d_in[10];
    const float* w_iou3 = (const float*)d_in[11];
    const float* b_iou3 = (const float*)d_in[12];
    const float* w_reg1 = (const float*)d_in[13];
    const float* w_reg2 = (const float*)d_in[14];
    const float* w_reg3 = (const float*)d_in[15];
    const float* b_reg3 = (const float*)d_in[16];

    float* out = (float*)d_out;
    int N = in_sizes[2];   // 2048

    float *part1, *bufL2;
    __nv_bfloat16 *xH, *xL, *aH, *aL, *shH, *shL, *l1H, *l1L;
    cudaGetSymbolAddress((void**)&part1, g_part1);
    cudaGetSymbolAddress((void**)&bufL2, g_bufL2);
    cudaGetSymbolAddress((void**)&xH, g_xH);
    cudaGetSymbolAddress((void**)&xL, g_xL);
    cudaGetSymbolAddress((void**)&aH, g_aH);
    cudaGetSymbolAddress((void**)&aL, g_aL);
    cudaGetSymbolAddress((void**)&shH, g_shH);
    cudaGetSymbolAddress((void**)&shL, g_shL);
    cudaGetSymbolAddress((void**)&l1H, g_l1H);
    cudaGetSymbolAddress((void**)&l1L, g_l1L);

    // 0) convert weights to bf16 hi/lo planes
    wconv_kernel<<<(WTOT / 4 + 255) / 256, 256>>>(w_sh1, w_sh2, w_cls1, w_cls2,
                                                  w_iou1, w_iou2, w_reg1, w_reg2);

    // 1) per-batch transpose -> ROI (ROI reads hit L2 while batch is resident)
    for (int b = 0; b < BB; b++) {
        transpose_kernel<<<dim3(HWSZ / 32, CC / 32), dim3(32, 8)>>>(fm, b);
        roi_kernel<<<N, 256>>>(boxes, bidx, b);
    }

    dim3 blk(128);
    size_t sND = (size_t)N * DD;
    int n4 = (int)(sND / 4);

    // 2) sh1: split-K x4 (K=2304 -> 4*576), fp32 partials, 512 CTAs
    gemm_bf16hl_kernel<<<dim3(DD / 64, N / 64, 4), blk>>>(
        xH, xL, 0, FEAT, FEAT / 4, 1,
        OFF_SH1, OFF_SH1, OFF_SH1, part1, nullptr, nullptr, sND, 0);

    // 2b) reduce partials + relu -> aH/aL (bf16 hi/lo)
    reduce4_relu_kernel<<<(n4 + 255) / 256, 256>>>(part1, n4);

    // 3) sh2 -> shH/shL
    gemm_bf16hl_kernel<<<dim3(DD / 64, N / 64, 1), blk>>>(
        aH, aL, 0, DD, DD, 0,
        OFF_SH2, OFF_SH2, OFF_SH2, nullptr, (unsigned*)shH, (unsigned*)shL, 0, 2);

    // 4) branch layer 1 (batched over 3 branches) -> l1H/l1L
    gemm_bf16hl_kernel<<<dim3(DD / 64, N / 64, 3), blk>>>(
        shH, shL, 0, DD, DD, 0,
        OFF_CLS1, OFF_IOU1, OFF_REG1, nullptr, (unsigned*)l1H, (unsigned*)l1L, sND, 2);

    // 5) branch layer 2 (batched) -> fp32 relu bufL2
    gemm_bf16hl_kernel<<<dim3(DD / 64, N / 64, 3), blk>>>(
        l1H, l1L, sND, DD, DD, 0,
        OFF_CLS2, OFF_IOU2, OFF_REG2, bufL2, nullptr, nullptr, sND, 1);

    // 6) all heads in one launch
    int hblocks = (3 * N * 32 + 255) / 256;
    head_all_kernel<<<hblocks, 256>>>(bufL2, w_cls3, b_cls3, w_iou3, b_iou3,
                                      w_reg3, b_reg3, out, N);
}

// round 11
// speedup vs baseline: 1.2585x; 1.2585x over previous
#include <cuda_runtime.h>
#include <cuda_bf16.h>
#include <cuda_fp16.h>
#include <math.h>

// Problem constants
#define BB    4
#define CC    256
#define HH    256
#define WW    256
#define HWSZ  (HH * WW)
#define NROI  2048
#define FEAT  2304          // 9 * 256
#define DD    256

// Weight-plane offsets (elements) into g_wH / g_wL
#define OFF_SH1   0
#define OFF_SH2   589824
#define OFF_CLS1  655360
#define OFF_CLS2  720896
#define OFF_IOU1  786432
#define OFF_IOU2  851968
#define OFF_REG1  917504
#define OFF_REG2  983040
#define WTOT      1048576

// Scratch (device globals; no allocation allowed)
__device__ __half         g_fmT[(size_t)BB * HWSZ * CC];     // [B,H,W,C] fp16
__device__ __nv_bfloat16  g_xH[(size_t)NROI * FEAT];
__device__ __nv_bfloat16  g_xL[(size_t)NROI * FEAT];
__device__ __nv_bfloat16  g_wH[WTOT];
__device__ __nv_bfloat16  g_wL[WTOT];
__device__ float          g_part1[(size_t)4 * NROI * DD];    // sh1 split-K partials
__device__ __nv_bfloat16  g_aH[(size_t)NROI * DD];
__device__ __nv_bfloat16  g_aL[(size_t)NROI * DD];
__device__ __nv_bfloat16  g_shH[(size_t)NROI * DD];
__device__ __nv_bfloat16  g_shL[(size_t)NROI * DD];
__device__ __nv_bfloat16  g_l1H[(size_t)3 * NROI * DD];
__device__ __nv_bfloat16  g_l1L[(size_t)3 * NROI * DD];
__device__ float          g_bufL2[(size_t)3 * NROI * DD];

// ---------------------------------------------------------------------------
// K0: transpose+convert [B,C,H,W] f32 -> [B,H,W,C] f16  (single launch)
// ---------------------------------------------------------------------------
__global__ __launch_bounds__(256) void transpose_kernel(const float* __restrict__ fm) {
    __shared__ float tile[32][33];
    int b   = blockIdx.z;
    int hw0 = blockIdx.x * 32;
    int c0  = blockIdx.y * 32;
    int tx = threadIdx.x, ty = threadIdx.y;      // 32 x 8
    const float* src = fm + (size_t)b * CC * HWSZ;
    #pragma unroll
    for (int k = 0; k < 4; k++) {
        int c = c0 + ty + 8 * k;
        tile[ty + 8 * k][tx] = src[(size_t)c * HWSZ + hw0 + tx];
    }
    __syncthreads();
    __half* dst = g_fmT + (size_t)b * HWSZ * CC;
    #pragma unroll
    for (int k = 0; k < 4; k++) {
        int hw = hw0 + ty + 8 * k;
        dst[(size_t)hw * CC + c0 + tx] = __float2half(tile[tx][ty + 8 * k]);
    }
}

// ---------------------------------------------------------------------------
// K1: rotated ROI align (all rois, one launch) -> bf16 hi/lo features
// ---------------------------------------------------------------------------
__global__ __launch_bounds__(256) void roi_kernel(const float* __restrict__ boxes,
                                                  const int* __restrict__ bidx) {
    int n = blockIdx.x;
    int c = threadIdx.x;   // channel

    __shared__ int   s_i00[36], s_i01[36], s_i10[36], s_i11[36];
    __shared__ float s_w[36][4];

    if (c < 36) {
        int s  = c;
        int ix = s & 1;
        int iy = (s >> 1) & 1;
        int p  = s >> 2;
        int pw = p % 3;
        int ph = p / 3;

        float b0 = boxes[n * 7 + 0];
        float b1 = boxes[n * 7 + 1];
        float b4 = boxes[n * 7 + 4];
        float b5 = boxes[n * 7 + 5];
        float b6 = boxes[n * 7 + 6];

        const float gw = 102.4f / 256.0f;
        float cx = (b0 + 51.2f) / gw - 0.5f;
        float cy = (b1 + 51.2f) / gw - 0.5f;
        float rw = b5 / gw;
        float rh = b4 / gw;
        float theta = -b6;
        float ct = cosf(theta), st = sinf(theta);
        float bin_h = rh / 3.0f, bin_w = rw / 3.0f;

        float sgy = ((float)iy + 0.5f) * 0.5f;
        float sgx = ((float)ix + 0.5f) * 0.5f;
        float yy = -rh * 0.5f + ((float)ph + sgy) * bin_h;
        float xx = -rw * 0.5f + ((float)pw + sgx) * bin_w;
        float y = yy * ct - xx * st + cy;
        float x = yy * st + xx * ct + cx;

        bool valid = (y > -1.0f) && (y < (float)HH) && (x > -1.0f) && (x < (float)WW);
        y = fminf(fmaxf(y, 0.0f), (float)(HH - 1));
        x = fminf(fmaxf(x, 0.0f), (float)(WW - 1));
        int y0 = min((int)floorf(y), HH - 1);
        int x0 = min((int)floorf(x), WW - 1);
        int y1 = min(y0 + 1, HH - 1);
        int x1 = min(x0 + 1, WW - 1);
        float ly = y - (float)y0, lx = x - (float)x0;
        float hy = 1.0f - ly, hx = 1.0f - lx;
        float v = valid ? 1.0f : 0.0f;

        s_i00[s] = y0 * WW + x0;
        s_i01[s] = y0 * WW + x1;
        s_i10[s] = y1 * WW + x0;
        s_i11[s] = y1 * WW + x1;
        s_w[s][0] = hy * hx * v;
        s_w[s][1] = hy * lx * v;
        s_w[s][2] = ly * hx * v;
        s_w[s][3] = ly * lx * v;
    }
    __syncthreads();

    int b = bidx[n];
    const __half* base = g_fmT + (size_t)b * HWSZ * CC + c;

    float acc[9];
    #pragma unroll
    for (int p = 0; p < 9; p++) acc[p] = 0.0f;

    #pragma unroll
    for (int s = 0; s < 36; s++) {
        float v = s_w[s][0] * __half2float(base[(size_t)s_i00[s] * CC])
                + s_w[s][1] * __half2float(base[(size_t)s_i01[s] * CC])
                + s_w[s][2] * __half2float(base[(size_t)s_i10[s] * CC])
                + s_w[s][3] * __half2float(base[(size_t)s_i11[s] * CC]);
        acc[s >> 2] += v;
    }

    size_t o = (size_t)n * FEAT + c;
    #pragma unroll
    for (int p = 0; p < 9; p++) {
        float val = acc[p] * 0.25f;
        __nv_bfloat16 h = __float2bfloat16(val);
        __nv_bfloat16 l = __float2bfloat16(val - __bfloat162float(h));
        g_xH[o + (size_t)p * CC] = h;
        g_xL[o + (size_t)p * CC] = l;
    }
}

// ---------------------------------------------------------------------------
// K1b: convert all GEMM weights to bf16 hi/lo planes (flat, float4 per thread)
// ---------------------------------------------------------------------------
__global__ __launch_bounds__(256) void wconv_kernel(
    const float* __restrict__ w_sh1, const float* __restrict__ w_sh2,
    const float* __restrict__ w_cls1, const float* __restrict__ w_cls2,
    const float* __restrict__ w_iou1, const float* __restrict__ w_iou2,
    const float* __restrict__ w_reg1, const float* __restrict__ w_reg2)
{
    int i4 = blockIdx.x * blockDim.x + threadIdx.x;
    if (i4 >= WTOT / 4) return;
    int idx = i4 * 4;

    const float* src;
    int loc;
    if      (idx < OFF_SH2)  { src = w_sh1;  loc = idx - OFF_SH1;  }
    else if (idx < OFF_CLS1) { src = w_sh2;  loc = idx - OFF_SH2;  }
    else if (idx < OFF_CLS2) { src = w_cls1; loc = idx - OFF_CLS1; }
    else if (idx < OFF_IOU1) { src = w_cls2; loc = idx - OFF_CLS2; }
    else if (idx < OFF_IOU2) { src = w_iou1; loc = idx - OFF_IOU1; }
    else if (idx < OFF_REG1) { src = w_iou2; loc = idx - OFF_IOU2; }
    else if (idx < OFF_REG2) { src = w_reg1; loc = idx - OFF_REG1; }
    else                     { src = w_reg2; loc = idx - OFF_REG2; }

    float4 v = *(const float4*)(src + loc);
    __nv_bfloat162 h0 = __floats2bfloat162_rn(v.x, v.y);
    __nv_bfloat162 l0 = __floats2bfloat162_rn(v.x - __low2float(h0), v.y - __high2float(h0));
    __nv_bfloat162 h1 = __floats2bfloat162_rn(v.z, v.w);
    __nv_bfloat162 l1 = __floats2bfloat162_rn(v.z - __low2float(h1), v.w - __high2float(h1));
    ((uint2*)g_wH)[i4] = make_uint2(*(unsigned*)&h0, *(unsigned*)&h1);
    ((uint2*)g_wL)[i4] = make_uint2(*(unsigned*)&l0, *(unsigned*)&l1);
}

// ---------------------------------------------------------------------------
// K2: 3xBF16 tensor-core GEMM, pre-converted bf16 hi/lo operands.
// C = [relu](A @ W^T);  D += aH*wH + aL*wH + aH*wL.
// CTA tile 64x64, 128 threads (4 warps of 32x32), k-step 16 (m16n8k16.bf16).
// smem: [64 rows][12 words]; word = bf16x2. Swizzle kw ^ 4*bit3(row).
//
//  kSplit=1: blockIdx.z picks k-chunk; out -> partial buffer z.
//  kSplit=0: blockIdx.z picks branch weight offset off0/1/2; A offset aZstride*z.
//  outMode: 0 = fp32 raw, 1 = fp32 relu, 2 = bf16 hi/lo relu
// ---------------------------------------------------------------------------
__device__ __forceinline__ void mma16(float* c, const unsigned* a, const unsigned* b) {
    asm volatile(
        "mma.sync.aligned.m16n8k16.row.col.f32.bf16.bf16.f32 "
        "{%0,%1,%2,%3}, {%4,%5,%6,%7}, {%8,%9}, {%0,%1,%2,%3};\n"
        : "+f"(c[0]), "+f"(c[1]), "+f"(c[2]), "+f"(c[3])
        : "r"(a[0]), "r"(a[1]), "r"(a[2]), "r"(a[3]), "r"(b[0]), "r"(b[1]));
}

__global__ __launch_bounds__(128) void gemm_bf16hl_kernel(
    const __nv_bfloat16* __restrict__ AH, const __nv_bfloat16* __restrict__ AL,
    size_t aZstride, int Krow, int Kchunk, int kSplit,
    size_t off0, size_t off1, size_t off2,
    float* __restrict__ Cf, unsigned* __restrict__ CH, unsigned* __restrict__ CL,
    size_t cZstride, int outMode)
{
    __shared__ unsigned AsH[64][12], AsL[64][12];
    __shared__ unsigned BsH[64][12], BsL[64][12];

    int z = blockIdx.z;
    size_t woff = kSplit ? off0 : ((z == 0) ? off0 : (z == 1) ? off1 : off2);
    int kBase = kSplit ? z * Kchunk : 0;
    size_t aoff = kSplit ? 0 : aZstride * (size_t)z;

    int row0 = blockIdx.y * 64, col0 = blockIdx.x * 64;
    int tid  = threadIdx.x;
    int warp = tid >> 5, lane = tid & 31;
    int g = lane >> 2, tg = lane & 3;
    int wm = (warp >> 1) * 32, wn = (warp & 1) * 32;

    int lr = tid >> 1;                              // 0..63 (smem row)
    int lq = (tid & 1) * 8;                         // k offset 0 or 8
    int sbase = (lq >> 1) ^ (((lr >> 3) & 1) << 2); // swizzled word base

    size_t abase = aoff + (size_t)(row0 + lr) * Krow + kBase + lq;
    size_t wbase = woff + (size_t)(col0 + lr) * Krow + kBase + lq;

    uint4 pa_h = *(const uint4*)(AH + abase);
    uint4 pa_l = *(const uint4*)(AL + abase);
    uint4 pw_h = *(const uint4*)(g_wH + wbase);
    uint4 pw_l = *(const uint4*)(g_wL + wbase);

    float acc[2][4][4];
    #pragma unroll
    for (int i = 0; i < 2; i++)
        #pragma unroll
        for (int j = 0; j < 4; j++)
            #pragma unroll
            for (int k = 0; k < 4; k++) acc[i][j][k] = 0.0f;

    for (int k0 = 0; k0 < Kchunk; k0 += 16) {
        __syncthreads();
        *(uint4*)&AsH[lr][sbase] = pa_h;
        *(uint4*)&AsL[lr][sbase] = pa_l;
        *(uint4*)&BsH[lr][sbase] = pw_h;
        *(uint4*)&BsL[lr][sbase] = pw_l;
        __syncthreads();

        if (k0 + 16 < Kchunk) {
            pa_h = *(const uint4*)(AH + abase + k0 + 16);
            pa_l = *(const uint4*)(AL + abase + k0 + 16);
            pw_h = *(const uint4*)(g_wH + wbase + k0 + 16);
            pw_l = *(const uint4*)(g_wL + wbase + k0 + 16);
        }

        unsigned aH[2][4], aL[2][4], bHf[4][2], bLf[4][2];
        #pragma unroll
        for (int mt = 0; mt < 2; mt++) {
            int r = wm + mt * 16 + g;        // bit3(r) = 0
            aH[mt][0] = AsH[r][tg];
            aH[mt][1] = AsH[r + 8][tg + 4];  // swizzled
            aH[mt][2] = AsH[r][tg + 4];
            aH[mt][3] = AsH[r + 8][tg];
            aL[mt][0] = AsL[r][tg];
            aL[mt][1] = AsL[r + 8][tg + 4];
            aL[mt][2] = AsL[r][tg + 4];
            aL[mt][3] = AsL[r + 8][tg];
        }
        #pragma unroll
        for (int nt = 0; nt < 4; nt++) {
            int nn = wn + nt * 8 + g;
            int s = (nt & 1) << 2;           // bit3(n) = nt&1
            bHf[nt][0] = BsH[nn][tg ^ s];
            bHf[nt][1] = BsH[nn][(tg + 4) ^ s];
            bLf[nt][0] = BsL[nn][tg ^ s];
            bLf[nt][1] = BsL[nn][(tg + 4) ^ s];
        }
        #pragma unroll
        for (int mt = 0; mt < 2; mt++)
            #pragma unroll
            for (int nt = 0; nt < 4; nt++) {
                mma16(acc[mt][nt], aH[mt], bHf[nt]);
                mma16(acc[mt][nt], aL[mt], bHf[nt]);
                mma16(acc[mt][nt], aH[mt], bLf[nt]);
            }
    }

    #pragma unroll
    for (int mt = 0; mt < 2; mt++) {
        int r = row0 + wm + mt * 16 + g;
        #pragma unroll
        for (int nt = 0; nt < 4; nt++) {
            int cb = col0 + wn + nt * 8 + 2 * tg;
            float v0 = acc[mt][nt][0], v1 = acc[mt][nt][1];
            float v2 = acc[mt][nt][2], v3 = acc[mt][nt][3];
            if (outMode >= 1) {
                v0 = fmaxf(v0, 0.0f); v1 = fmaxf(v1, 0.0f);
                v2 = fmaxf(v2, 0.0f); v3 = fmaxf(v3, 0.0f);
            }
            size_t i0 = cZstride * (size_t)z + (size_t)r * DD + cb;
            size_t i1 = cZstride * (size_t)z + (size_t)(r + 8) * DD + cb;
            if (outMode == 2) {
                __nv_bfloat162 h0 = __floats2bfloat162_rn(v0, v1);
                __nv_bfloat162 l0 = __floats2bfloat162_rn(v0 - __low2float(h0),
                                                          v1 - __high2float(h0));
                __nv_bfloat162 h1 = __floats2bfloat162_rn(v2, v3);
                __nv_bfloat162 l1 = __floats2bfloat162_rn(v2 - __low2float(h1),
                                                          v3 - __high2float(h1));
                CH[i0 >> 1] = *(unsigned*)&h0;
                CL[i0 >> 1] = *(unsigned*)&l0;
                CH[i1 >> 1] = *(unsigned*)&h1;
                CL[i1 >> 1] = *(unsigned*)&l1;
            } else {
                *(float2*)&Cf[i0] = make_float2(v0, v1);
                *(float2*)&Cf[i1] = make_float2(v2, v3);
            }
        }
    }
}

// ---------------------------------------------------------------------------
// K2b: reduce 4 split-K partials + relu -> bf16 hi/lo
// ---------------------------------------------------------------------------
__global__ __launch_bounds__(256) void reduce4_relu_kernel(
    const float* __restrict__ p, int n4)
{
    int i = blockIdx.x * blockDim.x + threadIdx.x;
    if (i >= n4) return;
    const float4* p4 = (const float4*)p;
    float4 a = p4[i];
    float4 b = p4[i + n4];
    float4 c = p4[i + 2 * n4];
    float4 d = p4[i + 3 * n4];
    float x = fmaxf(a.x + b.x + c.x + d.x, 0.0f);
    float y = fmaxf(a.y + b.y + c.y + d.y, 0.0f);
    float z = fmaxf(a.z + b.z + c.z + d.z, 0.0f);
    float w = fmaxf(a.w + b.w + c.w + d.w, 0.0f);
    __nv_bfloat162 h0 = __floats2bfloat162_rn(x, y);
    __nv_bfloat162 l0 = __floats2bfloat162_rn(x - __low2float(h0), y - __high2float(h0));
    __nv_bfloat162 h1 = __floats2bfloat162_rn(z, w);
    __nv_bfloat162 l1 = __floats2bfloat162_rn(z - __low2float(h1), w - __high2float(h1));
    ((uint2*)g_aH)[i] = make_uint2(*(unsigned*)&h0, *(unsigned*)&h1);
    ((uint2*)g_aL)[i] = make_uint2(*(unsigned*)&l0, *(unsigned*)&l1);
}

// ---------------------------------------------------------------------------
// K3: all three heads in one launch. Warp per (branch, row).
// ---------------------------------------------------------------------------
__global__ __launch_bounds__(256) void head_all_kernel(
    const float* __restrict__ Abase,
    const float* __restrict__ w_cls3, const float* __restrict__ b_cls3,
    const float* __restrict__ w_iou3, const float* __restrict__ b_iou3,
    const float* __restrict__ w_reg3, const float* __restrict__ b_reg3,
    float* __restrict__ out, int N)
{
    int gw   = (int)((blockIdx.x * blockDim.x + threadIdx.x) >> 5);
    int lane = threadIdx.x & 31;
    if (gw >= 3 * N) return;
    int br = gw / N, n = gw % N;

    const float* a = Abase + (size_t)br * N * DD + (size_t)n * DD;
    float av[8];
    #pragma unroll
    for (int i = 0; i < 8; i++) av[i] = a[lane + 32 * i];

    const float* Wm = (br == 0) ? w_cls3 : (br == 1) ? w_iou3 : w_reg3;
    const float* bs = (br == 0) ? b_cls3 : (br == 1) ? b_iou3 : b_reg3;
    int Dout = (br == 2) ? 7 : 1;
    float* o = out + ((br == 0) ? n : (br == 1) ? (N + n) : (2 * N + n * 7));

    for (int d = 0; d < Dout; d++) {
        const float* w = Wm + (size_t)d * DD;
        float s = 0.0f;
        #pragma unroll
        for (int i = 0; i < 8; i++) s = fmaf(av[i], w[lane + 32 * i], s);
        #pragma unroll
        for (int off = 16; off > 0; off >>= 1)
            s += __shfl_xor_sync(0xffffffffu, s, off);
        if (lane == 0) o[d] = s + bs[d];
    }
}

// ---------------------------------------------------------------------------
extern "C" void kernel_launch(void* const* d_in, const int* in_sizes, int n_in,
                              void* d_out, int out_size) {
    const float* fm     = (const float*)d_in[0];
    const float* boxes  = (const float*)d_in[1];
    const int*   bidx   = (const int*)  d_in[2];
    const float* w_sh1  = (const float*)d_in[3];
    const float* w_sh2  = (const float*)d_in[4];
    const float* w_cls1 = (const float*)d_in[5];
    const float* w_cls2 = (const float*)d_in[6];
    const float* w_cls3 = (const float*)d_in[7];
    const float* b_cls3 = (const float*)d_in[8];
    const float* w_iou1 = (const float*)d_in[9];
    const float* w_iou2 = (const float*)d_in[10];
    const float* w_iou3 = (const float*)d_in[11];
    const float* b_iou3 = (const float*)d_in[12];
    const float* w_reg1 = (const float*)d_in[13];
    const float* w_reg2 = (const float*)d_in[14];
    const float* w_reg3 = (const float*)d_in[15];
    const float* b_reg3 = (const float*)d_in[16];

    float* out = (float*)d_out;
    int N = in_sizes[2];   // 2048

    float *part1, *bufL2;
    __nv_bfloat16 *xH, *xL, *aH, *aL, *shH, *shL, *l1H, *l1L;
    cudaGetSymbolAddress((void**)&part1, g_part1);
    cudaGetSymbolAddress((void**)&bufL2, g_bufL2);
    cudaGetSymbolAddress((void**)&xH, g_xH);
    cudaGetSymbolAddress((void**)&xL, g_xL);
    cudaGetSymbolAddress((void**)&aH, g_aH);
    cudaGetSymbolAddress((void**)&aL, g_aL);
    cudaGetSymbolAddress((void**)&shH, g_shH);
    cudaGetSymbolAddress((void**)&shL, g_shL);
    cudaGetSymbolAddress((void**)&l1H, g_l1H);
    cudaGetSymbolAddress((void**)&l1L, g_l1L);

    // 0) convert weights to bf16 hi/lo planes
    wconv_kernel<<<(WTOT / 4 + 255) / 256, 256>>>(w_sh1, w_sh2, w_cls1, w_cls2,
                                                  w_iou1, w_iou2, w_reg1, w_reg2);

    // 1) transpose+convert feature map (single launch, all batches)
    transpose_kernel<<<dim3(HWSZ / 32, CC / 32, BB), dim3(32, 8)>>>(fm);

    // 2) rotated ROI align (single launch)
    roi_kernel<<<N, 256>>>(boxes, bidx);

    dim3 blk(128);
    size_t sND = (size_t)N * DD;
    int n4 = (int)(sND / 4);

    // 3) sh1: split-K x4 (K=2304 -> 4*576), fp32 partials, 512 CTAs
    gemm_bf16hl_kernel<<<dim3(DD / 64, N / 64, 4), blk>>>(
        xH, xL, 0, FEAT, FEAT / 4, 1,
        OFF_SH1, OFF_SH1, OFF_SH1, part1, nullptr, nullptr, sND, 0);

    // 3b) reduce partials + relu -> aH/aL (bf16 hi/lo)
    reduce4_relu_kernel<<<(n4 + 255) / 256, 256>>>(part1, n4);

    // 4) sh2 -> shH/shL
    gemm_bf16hl_kernel<<<dim3(DD / 64, N / 64, 1), blk>>>(
        aH, aL, 0, DD, DD, 0,
        OFF_SH2, OFF_SH2, OFF_SH2, nullptr, (unsigned*)shH, (unsigned*)shL, 0, 2);

    // 5) branch layer 1 (batched over 3 branches) -> l1H/l1L
    gemm_bf16hl_kernel<<<dim3(DD / 64, N / 64, 3), blk>>>(
        shH, shL, 0, DD, DD, 0,
        OFF_CLS1, OFF_IOU1, OFF_REG1, nullptr, (unsigned*)l1H, (unsigned*)l1L, sND, 2);

    // 6) branch layer 2 (batched) -> fp32 relu bufL2
    gemm_bf16hl_kernel<<<dim3(DD / 64, N / 64, 3), blk>>>(
        l1H, l1L, sND, DD, DD, 0,
        OFF_CLS2, OFF_IOU2, OFF_REG2, bufL2, nullptr, nullptr, sND, 1);

    // 7) all heads in one launch
    int hblocks = (3 * N * 32 + 255) / 256;
    head_all_kernel<<<hblocks, 256>>>(bufL2, w_cls3, b_cls3, w_iou3, b_iou3,
                                      w_reg3, b_reg3, out, N);
}

// round 12
// speedup vs baseline: 1.3204x; 1.0492x over previous
#include <cuda_runtime.h>
#include <cuda_bf16.h>
#include <cuda_fp16.h>
#include <math.h>

// Problem constants
#define BB    4
#define CC    256
#define HH    256
#define WW    256
#define HWSZ  (HH * WW)
#define NROI  2048
#define FEAT  2304          // 9 * 256
#define DD    256

// Weight-plane offsets (elements) into g_wH / g_wL
#define OFF_SH1   0
#define OFF_SH2   589824
#define OFF_CLS1  655360
#define OFF_CLS2  720896
#define OFF_IOU1  786432
#define OFF_IOU2  851968
#define OFF_REG1  917504
#define OFF_REG2  983040
#define WTOT      1048576

#define KSPLIT1   8

// Scratch (device globals; no allocation allowed)
__device__ __half         g_fmT[(size_t)BB * HWSZ * CC];     // [B,H,W,C] fp16
__device__ __nv_bfloat16  g_xH[(size_t)NROI * FEAT];
__device__ __nv_bfloat16  g_xL[(size_t)NROI * FEAT];
__device__ __nv_bfloat16  g_wH[WTOT];
__device__ __nv_bfloat16  g_wL[WTOT];
__device__ float          g_part1[(size_t)KSPLIT1 * NROI * DD];
__device__ __nv_bfloat16  g_aH[(size_t)NROI * DD];
__device__ __nv_bfloat16  g_aL[(size_t)NROI * DD];
__device__ __nv_bfloat16  g_shH[(size_t)NROI * DD];
__device__ __nv_bfloat16  g_shL[(size_t)NROI * DD];
__device__ __nv_bfloat16  g_l1H[(size_t)3 * NROI * DD];
__device__ __nv_bfloat16  g_l1L[(size_t)3 * NROI * DD];
__device__ float          g_bufL2[(size_t)3 * NROI * DD];

// ---------------------------------------------------------------------------
// K0: transpose+convert [B,C,H,W] f32 -> [B,H,W,C] f16  (single launch)
// ---------------------------------------------------------------------------
__global__ __launch_bounds__(256) void transpose_kernel(const float* __restrict__ fm) {
    __shared__ float tile[32][33];
    int b   = blockIdx.z;
    int hw0 = blockIdx.x * 32;
    int c0  = blockIdx.y * 32;
    int tx = threadIdx.x, ty = threadIdx.y;      // 32 x 8
    const float* src = fm + (size_t)b * CC * HWSZ;
    #pragma unroll
    for (int k = 0; k < 4; k++) {
        int c = c0 + ty + 8 * k;
        tile[ty + 8 * k][tx] = src[(size_t)c * HWSZ + hw0 + tx];
    }
    __syncthreads();
    __half* dst = g_fmT + (size_t)b * HWSZ * CC;
    #pragma unroll
    for (int k = 0; k < 4; k++) {
        int hw = hw0 + ty + 8 * k;
        dst[(size_t)hw * CC + c0 + tx] = __float2half(tile[tx][ty + 8 * k]);
    }
}

// ---------------------------------------------------------------------------
// K1: rotated ROI align (all rois, one launch) -> bf16 hi/lo features
// ---------------------------------------------------------------------------
__global__ __launch_bounds__(256) void roi_kernel(const float* __restrict__ boxes,
                                                  const int* __restrict__ bidx) {
    int n = blockIdx.x;
    int c = threadIdx.x;   // channel

    __shared__ int   s_i00[36], s_i01[36], s_i10[36], s_i11[36];
    __shared__ float s_w[36][4];

    if (c < 36) {
        int s  = c;
        int ix = s & 1;
        int iy = (s >> 1) & 1;
        int p  = s >> 2;
        int pw = p % 3;
        int ph = p / 3;

        float b0 = boxes[n * 7 + 0];
        float b1 = boxes[n * 7 + 1];
        float b4 = boxes[n * 7 + 4];
        float b5 = boxes[n * 7 + 5];
        float b6 = boxes[n * 7 + 6];

        const float gw = 102.4f / 256.0f;
        float cx = (b0 + 51.2f) / gw - 0.5f;
        float cy = (b1 + 51.2f) / gw - 0.5f;
        float rw = b5 / gw;
        float rh = b4 / gw;
        float theta = -b6;
        float ct = cosf(theta), st = sinf(theta);
        float bin_h = rh / 3.0f, bin_w = rw / 3.0f;

        float sgy = ((float)iy + 0.5f) * 0.5f;
        float sgx = ((float)ix + 0.5f) * 0.5f;
        float yy = -rh * 0.5f + ((float)ph + sgy) * bin_h;
        float xx = -rw * 0.5f + ((float)pw + sgx) * bin_w;
        float y = yy * ct - xx * st + cy;
        float x = yy * st + xx * ct + cx;

        bool valid = (y > -1.0f) && (y < (float)HH) && (x > -1.0f) && (x < (float)WW);
        y = fminf(fmaxf(y, 0.0f), (float)(HH - 1));
        x = fminf(fmaxf(x, 0.0f), (float)(WW - 1));
        int y0 = min((int)floorf(y), HH - 1);
        int x0 = min((int)floorf(x), WW - 1);
        int y1 = min(y0 + 1, HH - 1);
        int x1 = min(x0 + 1, WW - 1);
        float ly = y - (float)y0, lx = x - (float)x0;
        float hy = 1.0f - ly, hx = 1.0f - lx;
        float v = valid ? 1.0f : 0.0f;

        s_i00[s] = y0 * WW + x0;
        s_i01[s] = y0 * WW + x1;
        s_i10[s] = y1 * WW + x0;
        s_i11[s] = y1 * WW + x1;
        s_w[s][0] = hy * hx * v;
        s_w[s][1] = hy * lx * v;
        s_w[s][2] = ly * hx * v;
        s_w[s][3] = ly * lx * v;
    }
    __syncthreads();

    int b = bidx[n];
    const __half* base = g_fmT + (size_t)b * HWSZ * CC + c;

    float acc[9];
    #pragma unroll
    for (int p = 0; p < 9; p++) acc[p] = 0.0f;

    #pragma unroll
    for (int s = 0; s < 36; s++) {
        float v = s_w[s][0] * __half2float(base[(size_t)s_i00[s] * CC])
                + s_w[s][1] * __half2float(base[(size_t)s_i01[s] * CC])
                + s_w[s][2] * __half2float(base[(size_t)s_i10[s] * CC])
                + s_w[s][3] * __half2float(base[(size_t)s_i11[s] * CC]);
        acc[s >> 2] += v;
    }

    size_t o = (size_t)n * FEAT + c;
    #pragma unroll
    for (int p = 0; p < 9; p++) {
        float val = acc[p] * 0.25f;
        __nv_bfloat16 h = __float2bfloat16(val);
        __nv_bfloat16 l = __float2bfloat16(val - __bfloat162float(h));
        g_xH[o + (size_t)p * CC] = h;
        g_xL[o + (size_t)p * CC] = l;
    }
}

// ---------------------------------------------------------------------------
// K1b: convert all GEMM weights to bf16 hi/lo planes
// ---------------------------------------------------------------------------
__global__ __launch_bounds__(256) void wconv_kernel(
    const float* __restrict__ w_sh1, const float* __restrict__ w_sh2,
    const float* __restrict__ w_cls1, const float* __restrict__ w_cls2,
    const float* __restrict__ w_iou1, const float* __restrict__ w_iou2,
    const float* __restrict__ w_reg1, const float* __restrict__ w_reg2)
{
    int i4 = blockIdx.x * blockDim.x + threadIdx.x;
    if (i4 >= WTOT / 4) return;
    int idx = i4 * 4;

    const float* src;
    int loc;
    if      (idx < OFF_SH2)  { src = w_sh1;  loc = idx - OFF_SH1;  }
    else if (idx < OFF_CLS1) { src = w_sh2;  loc = idx - OFF_SH2;  }
    else if (idx < OFF_CLS2) { src = w_cls1; loc = idx - OFF_CLS1; }
    else if (idx < OFF_IOU1) { src = w_cls2; loc = idx - OFF_CLS2; }
    else if (idx < OFF_IOU2) { src = w_iou1; loc = idx - OFF_IOU1; }
    else if (idx < OFF_REG1) { src = w_iou2; loc = idx - OFF_IOU2; }
    else if (idx < OFF_REG2) { src = w_reg1; loc = idx - OFF_REG1; }
    else                     { src = w_reg2; loc = idx - OFF_REG2; }

    float4 v = *(const float4*)(src + loc);
    __nv_bfloat162 h0 = __floats2bfloat162_rn(v.x, v.y);
    __nv_bfloat162 l0 = __floats2bfloat162_rn(v.x - __low2float(h0), v.y - __high2float(h0));
    __nv_bfloat162 h1 = __floats2bfloat162_rn(v.z, v.w);
    __nv_bfloat162 l1 = __floats2bfloat162_rn(v.z - __low2float(h1), v.w - __high2float(h1));
    ((uint2*)g_wH)[i4] = make_uint2(*(unsigned*)&h0, *(unsigned*)&h1);
    ((uint2*)g_wL)[i4] = make_uint2(*(unsigned*)&l0, *(unsigned*)&l1);
}

// ---------------------------------------------------------------------------
// K2: 3xBF16 tensor-core GEMM; pre-converted hi/lo operands; double-buffered
// smem; ldmatrix fragment loads.  D += aH*wH + aL*wH + aH*wL.
// CTA 64x64, 128 threads (4 warps of 32x32), k-step 16.
// smem row: 8 words (bf16x2), swizzled word = 4*(kgroup ^ bit3(row)), pitch 12.
// ---------------------------------------------------------------------------
__device__ __forceinline__ void mma16(float* c, const unsigned* a, const unsigned* b) {
    asm volatile(
        "mma.sync.aligned.m16n8k16.row.col.f32.bf16.bf16.f32 "
        "{%0,%1,%2,%3}, {%4,%5,%6,%7}, {%8,%9}, {%0,%1,%2,%3};\n"
        : "+f"(c[0]), "+f"(c[1]), "+f"(c[2]), "+f"(c[3])
        : "r"(a[0]), "r"(a[1]), "r"(a[2]), "r"(a[3]), "r"(b[0]), "r"(b[1]));
}

__device__ __forceinline__ void ldsm4(unsigned& r0, unsigned& r1,
                                      unsigned& r2, unsigned& r3, unsigned addr) {
    asm volatile(
        "ldmatrix.sync.aligned.m8n8.x4.shared.b16 {%0,%1,%2,%3}, [%4];"
        : "=r"(r0), "=r"(r1), "=r"(r2), "=r"(r3) : "r"(addr));
}

#define SROW 12   // words per smem row (pitch)

__global__ __launch_bounds__(128) void gemm_bf16hl_kernel(
    const __nv_bfloat16* __restrict__ AH, const __nv_bfloat16* __restrict__ AL,
    size_t aZstride, int Krow, int Kchunk, int kSplit,
    size_t off0, size_t off1, size_t off2,
    float* __restrict__ Cf, unsigned* __restrict__ CH, unsigned* __restrict__ CL,
    size_t cZstride, int outMode)
{
    __shared__ unsigned AsH[2][64][SROW], AsL[2][64][SROW];
    __shared__ unsigned BsH[2][64][SROW], BsL[2][64][SROW];

    int z = blockIdx.z;
    size_t woff = kSplit ? off0 : ((z == 0) ? off0 : (z == 1) ? off1 : off2);
    int kBase = kSplit ? z * Kchunk : 0;
    size_t aoff = kSplit ? 0 : aZstride * (size_t)z;

    int row0 = blockIdx.y * 64, col0 = blockIdx.x * 64;
    int tid  = threadIdx.x;
    int warp = tid >> 5, lane = tid & 31;
    int g = lane >> 2, tg = lane & 3;
    int wm = (warp >> 1) * 32, wn = (warp & 1) * 32;

    int lr = tid >> 1;                              // 0..63 (smem row)
    int lq = (tid & 1) * 8;                         // k offset 0 or 8
    int sbase = (lq >> 1) ^ (((lr >> 3) & 1) << 2); // swizzled word base

    size_t abase = aoff + (size_t)(row0 + lr) * Krow + kBase + lq;
    size_t wbase = woff + (size_t)(col0 + lr) * Krow + kBase + lq;

    // ldmatrix lane addressing (byte offsets within one [64][SROW] plane)
    unsigned sub = lane >> 3, rowoff = lane & 7;
    // A tile: matrices {row,k0},{row+8,k0},{row,k8},{row+8,k8}
    int arow = wm + ((sub & 1) << 3) + rowoff;      // + mt*16 added per use
    int aj   = sub >> 1;
    // B pair: matrices {n(p0),k0},{n(p0),k8},{n(p1),k0},{n(p1),k8}
    int brow = wn + ((sub >> 1) << 3) + rowoff;     // + pair*16 added per use
    int bj   = sub & 1;

    unsigned baseAH = (unsigned)__cvta_generic_to_shared(&AsH[0][0][0]);
    unsigned baseAL = (unsigned)__cvta_generic_to_shared(&AsL[0][0][0]);
    unsigned baseBH = (unsigned)__cvta_generic_to_shared(&BsH[0][0][0]);
    unsigned baseBL = (unsigned)__cvta_generic_to_shared(&BsL[0][0][0]);
    const unsigned planeBytes = 64 * SROW * 4;

    uint4 pa_h = *(const uint4*)(AH + abase);
    uint4 pa_l = *(const uint4*)(AL + abase);
    uint4 pw_h = *(const uint4*)(g_wH + wbase);
    uint4 pw_l = *(const uint4*)(g_wL + wbase);

    float acc[2][4][4];
    #pragma unroll
    for (int i = 0; i < 2; i++)
        #pragma unroll
        for (int j = 0; j < 4; j++)
            #pragma unroll
            for (int k = 0; k < 4; k++) acc[i][j][k] = 0.0f;

    // prologue: fill stage 0
    *(uint4*)&AsH[0][lr][sbase] = pa_h;
    *(uint4*)&AsL[0][lr][sbase] = pa_l;
    *(uint4*)&BsH[0][lr][sbase] = pw_h;
    *(uint4*)&BsL[0][lr][sbase] = pw_l;
    __syncthreads();

    int nIter = Kchunk / 16;
    for (int it = 0; it < nIter; it++) {
        int cur = it & 1, nxt = cur ^ 1;
        bool hasNext = (it + 1 < nIter);

        if (hasNext) {
            int ko = (it + 1) * 16;
            pa_h = *(const uint4*)(AH + abase + ko);
            pa_l = *(const uint4*)(AL + abase + ko);
            pw_h = *(const uint4*)(g_wH + wbase + ko);
            pw_l = *(const uint4*)(g_wL + wbase + ko);
        }

        // fragment loads via ldmatrix
        unsigned aH[2][4], aL[2][4], bHf[4][2], bLf[4][2];
        unsigned curOff = cur * planeBytes;
        #pragma unroll
        for (int mt = 0; mt < 2; mt++) {
            int r = arow + mt * 16;
            unsigned boff = curOff + (r * SROW + 4 * (aj ^ ((r >> 3) & 1))) * 4;
            ldsm4(aH[mt][0], aH[mt][1], aH[mt][2], aH[mt][3], baseAH + boff);
            ldsm4(aL[mt][0], aL[mt][1], aL[mt][2], aL[mt][3], baseAL + boff);
        }
        #pragma unroll
        for (int p = 0; p < 2; p++) {
            int nn = brow + p * 16;
            unsigned boff = curOff + (nn * SROW + 4 * (bj ^ ((nn >> 3) & 1))) * 4;
            ldsm4(bHf[2*p][0], bHf[2*p][1], bHf[2*p+1][0], bHf[2*p+1][1], baseBH + boff);
            ldsm4(bLf[2*p][0], bLf[2*p][1], bLf[2*p+1][0], bLf[2*p+1][1], baseBL + boff);
        }

        if (hasNext) {
            *(uint4*)&AsH[nxt][lr][sbase] = pa_h;
            *(uint4*)&AsL[nxt][lr][sbase] = pa_l;
            *(uint4*)&BsH[nxt][lr][sbase] = pw_h;
            *(uint4*)&BsL[nxt][lr][sbase] = pw_l;
        }

        #pragma unroll
        for (int mt = 0; mt < 2; mt++)
            #pragma unroll
            for (int nt = 0; nt < 4; nt++) {
                mma16(acc[mt][nt], aH[mt], bHf[nt]);
                mma16(acc[mt][nt], aL[mt], bHf[nt]);
                mma16(acc[mt][nt], aH[mt], bLf[nt]);
            }

        __syncthreads();
    }

    #pragma unroll
    for (int mt = 0; mt < 2; mt++) {
        int r = row0 + wm + mt * 16 + g;
        #pragma unroll
        for (int nt = 0; nt < 4; nt++) {
            int cb = col0 + wn + nt * 8 + 2 * tg;
            float v0 = acc[mt][nt][0], v1 = acc[mt][nt][1];
            float v2 = acc[mt][nt][2], v3 = acc[mt][nt][3];
            if (outMode >= 1) {
                v0 = fmaxf(v0, 0.0f); v1 = fmaxf(v1, 0.0f);
                v2 = fmaxf(v2, 0.0f); v3 = fmaxf(v3, 0.0f);
            }
            size_t i0 = cZstride * (size_t)z + (size_t)r * DD + cb;
            size_t i1 = cZstride * (size_t)z + (size_t)(r + 8) * DD + cb;
            if (outMode == 2) {
                __nv_bfloat162 h0 = __floats2bfloat162_rn(v0, v1);
                __nv_bfloat162 l0 = __floats2bfloat162_rn(v0 - __low2float(h0),
                                                          v1 - __high2float(h0));
                __nv_bfloat162 h1 = __floats2bfloat162_rn(v2, v3);
                __nv_bfloat162 l1 = __floats2bfloat162_rn(v2 - __low2float(h1),
                                                          v3 - __high2float(h1));
                CH[i0 >> 1] = *(unsigned*)&h0;
                CL[i0 >> 1] = *(unsigned*)&l0;
                CH[i1 >> 1] = *(unsigned*)&h1;
                CL[i1 >> 1] = *(unsigned*)&l1;
            } else {
                *(float2*)&Cf[i0] = make_float2(v0, v1);
                *(float2*)&Cf[i1] = make_float2(v2, v3);
            }
        }
    }
}

// ---------------------------------------------------------------------------
// K2b: reduce KSPLIT1 split-K partials + relu -> bf16 hi/lo
// ---------------------------------------------------------------------------
__global__ __launch_bounds__(256) void reduceN_relu_kernel(
    const float* __restrict__ p, int n4)
{
    int i = blockIdx.x * blockDim.x + threadIdx.x;
    if (i >= n4) return;
    const float4* p4 = (const float4*)p;
    float4 s = p4[i];
    #pragma unroll
    for (int j = 1; j < KSPLIT1; j++) {
        float4 q = p4[i + (size_t)j * n4];
        s.x += q.x; s.y += q.y; s.z += q.z; s.w += q.w;
    }
    float x = fmaxf(s.x, 0.0f), y = fmaxf(s.y, 0.0f);
    float z = fmaxf(s.z, 0.0f), w = fmaxf(s.w, 0.0f);
    __nv_bfloat162 h0 = __floats2bfloat162_rn(x, y);
    __nv_bfloat162 l0 = __floats2bfloat162_rn(x - __low2float(h0), y - __high2float(h0));
    __nv_bfloat162 h1 = __floats2bfloat162_rn(z, w);
    __nv_bfloat162 l1 = __floats2bfloat162_rn(z - __low2float(h1), w - __high2float(h1));
    ((uint2*)g_aH)[i] = make_uint2(*(unsigned*)&h0, *(unsigned*)&h1);
    ((uint2*)g_aL)[i] = make_uint2(*(unsigned*)&l0, *(unsigned*)&l1);
}

// ---------------------------------------------------------------------------
// K3: all three heads in one launch. Warp per (branch, row).
// ---------------------------------------------------------------------------
__global__ __launch_bounds__(256) void head_all_kernel(
    const float* __restrict__ Abase,
    const float* __restrict__ w_cls3, const float* __restrict__ b_cls3,
    const float* __restrict__ w_iou3, const float* __restrict__ b_iou3,
    const float* __restrict__ w_reg3, const float* __restrict__ b_reg3,
    float* __restrict__ out, int N)
{
    int gw   = (int)((blockIdx.x * blockDim.x + threadIdx.x) >> 5);
    int lane = threadIdx.x & 31;
    if (gw >= 3 * N) return;
    int br = gw / N, n = gw % N;

    const float* a = Abase + (size_t)br * N * DD + (size_t)n * DD;
    float av[8];
    #pragma unroll
    for (int i = 0; i < 8; i++) av[i] = a[lane + 32 * i];

    const float* Wm = (br == 0) ? w_cls3 : (br == 1) ? w_iou3 : w_reg3;
    const float* bs = (br == 0) ? b_cls3 : (br == 1) ? b_iou3 : b_reg3;
    int Dout = (br == 2) ? 7 : 1;
    float* o = out + ((br == 0) ? n : (br == 1) ? (N + n) : (2 * N + n * 7));

    for (int d = 0; d < Dout; d++) {
        const float* w = Wm + (size_t)d * DD;
        float s = 0.0f;
        #pragma unroll
        for (int i = 0; i < 8; i++) s = fmaf(av[i], w[lane + 32 * i], s);
        #pragma unroll
        for (int off = 16; off > 0; off >>= 1)
            s += __shfl_xor_sync(0xffffffffu, s, off);
        if (lane == 0) o[d] = s + bs[d];
    }
}

// ---------------------------------------------------------------------------
extern "C" void kernel_launch(void* const* d_in, const int* in_sizes, int n_in,
                              void* d_out, int out_size) {
    const float* fm     = (const float*)d_in[0];
    const float* boxes  = (const float*)d_in[1];
    const int*   bidx   = (const int*)  d_in[2];
    const float* w_sh1  = (const float*)d_in[3];
    const float* w_sh2  = (const float*)d_in[4];
    const float* w_cls1 = (const float*)d_in[5];
    const float* w_cls2 = (const float*)d_in[6];
    const float* w_cls3 = (const float*)d_in[7];
    const float* b_cls3 = (const float*)d_in[8];
    const float* w_iou1 = (const float*)d_in[9];
    const float* w_iou2 = (const float*)d_in[10];
    const float* w_iou3 = (const float*)d_in[11];
    const float* b_iou3 = (const float*)d_in[12];
    const float* w_reg1 = (const float*)d_in[13];
    const float* w_reg2 = (const float*)d_in[14];
    const float* w_reg3 = (const float*)d_in[15];
    const float* b_reg3 = (const float*)d_in[16];

    float* out = (float*)d_out;
    int N = in_sizes[2];   // 2048

    float *part1, *bufL2;
    __nv_bfloat16 *xH, *xL, *aH, *aL, *shH, *shL, *l1H, *l1L;
    cudaGetSymbolAddress((void**)&part1, g_part1);
    cudaGetSymbolAddress((void**)&bufL2, g_bufL2);
    cudaGetSymbolAddress((void**)&xH, g_xH);
    cudaGetSymbolAddress((void**)&xL, g_xL);
    cudaGetSymbolAddress((void**)&aH, g_aH);
    cudaGetSymbolAddress((void**)&aL, g_aL);
    cudaGetSymbolAddress((void**)&shH, g_shH);
    cudaGetSymbolAddress((void**)&shL, g_shL);
    cudaGetSymbolAddress((void**)&l1H, g_l1H);
    cudaGetSymbolAddress((void**)&l1L, g_l1L);

    // 0) convert weights to bf16 hi/lo planes
    wconv_kernel<<<(WTOT / 4 + 255) / 256, 256>>>(w_sh1, w_sh2, w_cls1, w_cls2,
                                                  w_iou1, w_iou2, w_reg1, w_reg2);

    // 1) transpose+convert feature map
    transpose_kernel<<<dim3(HWSZ / 32, CC / 32, BB), dim3(32, 8)>>>(fm);

    // 2) rotated ROI align
    roi_kernel<<<N, 256>>>(boxes, bidx);

    dim3 blk(128);
    size_t sND = (size_t)N * DD;
    int n4 = (int)(sND / 4);

    // 3) sh1: split-K x8 (K=2304 -> 8*288), fp32 partials, 1024 CTAs
    gemm_bf16hl_kernel<<<dim3(DD / 64, N / 64, KSPLIT1), blk>>>(
        xH, xL, 0, FEAT, FEAT / KSPLIT1, 1,
        OFF_SH1, OFF_SH1, OFF_SH1, part1, nullptr, nullptr, sND, 0);

    // 3b) reduce partials + relu -> aH/aL (bf16 hi/lo)
    reduceN_relu_kernel<<<(n4 + 255) / 256, 256>>>(part1, n4);

    // 4) sh2 -> shH/shL
    gemm_bf16hl_kernel<<<dim3(DD / 64, N / 64, 1), blk>>>(
        aH, aL, 0, DD, DD, 0,
        OFF_SH2, OFF_SH2, OFF_SH2, nullptr, (unsigned*)shH, (unsigned*)shL, 0, 2);

    // 5) branch layer 1 (batched over 3 branches) -> l1H/l1L
    gemm_bf16hl_kernel<<<dim3(DD / 64, N / 64, 3), blk>>>(
        shH, shL, 0, DD, DD, 0,
        OFF_CLS1, OFF_IOU1, OFF_REG1, nullptr, (unsigned*)l1H, (unsigned*)l1L, sND, 2);

    // 6) branch layer 2 (batched) -> fp32 relu bufL2
    gemm_bf16hl_kernel<<<dim3(DD / 64, N / 64, 3), blk>>>(
        l1H, l1L, sND, DD, DD, 0,
        OFF_CLS2, OFF_IOU2, OFF_REG2, bufL2, nullptr, nullptr, sND, 1);

    // 7) all heads in one launch
    int hblocks = (3 * N * 32 + 255) / 256;
    head_all_kernel<<<hblocks, 256>>>(bufL2, w_cls3, b_cls3, w_iou3, b_iou3,
                                      w_reg3, b_reg3, out, N);
}

// round 14
// speedup vs baseline: 1.6160x; 1.2239x over previous
#include <cuda_runtime.h>
#include <cuda_bf16.h>
#include <cuda_fp16.h>
#include <math.h>

// Problem constants
#define BB    4
#define CC    256
#define HH    256
#define WW    256
#define HWSZ  (HH * WW)
#define NROI  2048
#define FEAT  2304          // 9 * 256
#define DD    256

// Weight-plane offsets (elements) into g_wH / g_wL
#define OFF_SH1   0
#define OFF_SH2   589824
#define OFF_CLS1  655360
#define OFF_CLS2  720896
#define OFF_IOU1  786432
#define OFF_IOU2  851968
#define OFF_REG1  917504
#define OFF_REG2  983040
#define WTOT      1048576

#define KSPLIT1   9          // 2304/9 = 256-K chunks; grid 288 = 2 balanced waves

// Scratch (device globals; no allocation allowed)
__device__ __half         g_fmT[(size_t)BB * HWSZ * CC];     // [B,H,W,C] fp16
__device__ __nv_bfloat16  g_xH[(size_t)NROI * FEAT];
__device__ __nv_bfloat16  g_xL[(size_t)NROI * FEAT];
__device__ __nv_bfloat16  g_wH[WTOT];
__device__ __nv_bfloat16  g_wL[WTOT];
__device__ float          g_part1[(size_t)KSPLIT1 * NROI * DD];
__device__ __nv_bfloat16  g_aH[(size_t)NROI * DD];
__device__ __nv_bfloat16  g_aL[(size_t)NROI * DD];
__device__ __nv_bfloat16  g_shH[(size_t)NROI * DD];
__device__ __nv_bfloat16  g_shL[(size_t)NROI * DD];
__device__ __nv_bfloat16  g_l1H[(size_t)3 * NROI * DD];
__device__ __nv_bfloat16  g_l1L[(size_t)3 * NROI * DD];
__device__ float          g_bufL2[(size_t)3 * NROI * DD];

// ---------------------------------------------------------------------------
// K0: transpose+convert [B,C,H,W] f32 -> [B,H,W,C] f16
// Tile 32hw x 64c; reads 128B/warp; writes half2 -> 128B/warp coalesced.
// ---------------------------------------------------------------------------
__global__ __launch_bounds__(256) void transpose_kernel(const float* __restrict__ fm) {
    __shared__ float tile[32][65];   // [hw][c] pad 65 -> conflict-free phase1
    int b   = blockIdx.z;
    int hw0 = blockIdx.x * 32;
    int c0  = blockIdx.y * 64;
    int tx = threadIdx.x, ty = threadIdx.y;      // 32 x 8
    const float* src = fm + (size_t)b * CC * HWSZ;
    #pragma unroll
    for (int k = 0; k < 8; k++) {
        int c = ty + 8 * k;                      // 0..63
        tile[tx][c] = src[(size_t)(c0 + c) * HWSZ + hw0 + tx];
    }
    __syncthreads();
    __half* dst = g_fmT + (size_t)b * HWSZ * CC;
    #pragma unroll
    for (int k = 0; k < 4; k++) {
        int hw = ty + 8 * k;                     // 0..31
        float x = tile[hw][2 * tx];
        float y = tile[hw][2 * tx + 1];
        __half2 h = __floats2half2_rn(x, y);
        *(__half2*)&dst[(size_t)(hw0 + hw) * CC + c0 + 2 * tx] = h;
    }
}

// ---------------------------------------------------------------------------
// K1: rotated ROI align -> bf16 hi/lo features. 128 thr, half2 channel pairs.
// ---------------------------------------------------------------------------
__global__ __launch_bounds__(128) void roi_kernel(const float* __restrict__ boxes,
                                                  const int* __restrict__ bidx) {
    int n = blockIdx.x;
    int c2 = threadIdx.x;   // channel pair index (0..127)

    __shared__ int   s_i00[36], s_i01[36], s_i10[36], s_i11[36];
    __shared__ float s_w[36][4];

    if (c2 < 36) {
        int s  = c2;
        int ix = s & 1;
        int iy = (s >> 1) & 1;
        int p  = s >> 2;
        int pw = p % 3;
        int ph = p / 3;

        float b0 = boxes[n * 7 + 0];
        float b1 = boxes[n * 7 + 1];
        float b4 = boxes[n * 7 + 4];
        float b5 = boxes[n * 7 + 5];
        float b6 = boxes[n * 7 + 6];

        const float gw = 102.4f / 256.0f;
        float cx = (b0 + 51.2f) / gw - 0.5f;
        float cy = (b1 + 51.2f) / gw - 0.5f;
        float rw = b5 / gw;
        float rh = b4 / gw;
        float theta = -b6;
        float ct = cosf(theta), st = sinf(theta);
        float bin_h = rh / 3.0f, bin_w = rw / 3.0f;

        float sgy = ((float)iy + 0.5f) * 0.5f;
        float sgx = ((float)ix + 0.5f) * 0.5f;
        float yy = -rh * 0.5f + ((float)ph + sgy) * bin_h;
        float xx = -rw * 0.5f + ((float)pw + sgx) * bin_w;
        float y = yy * ct - xx * st + cy;
        float x = yy * st + xx * ct + cx;

        bool valid = (y > -1.0f) && (y < (float)HH) && (x > -1.0f) && (x < (float)WW);
        y = fminf(fmaxf(y, 0.0f), (float)(HH - 1));
        x = fminf(fmaxf(x, 0.0f), (float)(WW - 1));
        int y0 = min((int)floorf(y), HH - 1);
        int x0 = min((int)floorf(x), WW - 1);
        int y1 = min(y0 + 1, HH - 1);
        int x1 = min(x0 + 1, WW - 1);
        float ly = y - (float)y0, lx = x - (float)x0;
        float hy = 1.0f - ly, hx = 1.0f - lx;
        float v = valid ? 1.0f : 0.0f;

        s_i00[s] = y0 * WW + x0;
        s_i01[s] = y0 * WW + x1;
        s_i10[s] = y1 * WW + x0;
        s_i11[s] = y1 * WW + x1;
        s_w[s][0] = hy * hx * v;
        s_w[s][1] = hy * lx * v;
        s_w[s][2] = ly * hx * v;
        s_w[s][3] = ly * lx * v;
    }
    __syncthreads();

    int b = bidx[n];
    const __half* base = g_fmT + (size_t)b * HWSZ * CC + 2 * c2;

    float2 acc[9];
    #pragma unroll
    for (int p = 0; p < 9; p++) acc[p] = make_float2(0.0f, 0.0f);

    #pragma unroll
    for (int s = 0; s < 36; s++) {
        float2 v00 = __half22float2(*(const __half2*)&base[(size_t)s_i00[s] * CC]);
        float2 v01 = __half22float2(*(const __half2*)&base[(size_t)s_i01[s] * CC]);
        float2 v10 = __half22float2(*(const __half2*)&base[(size_t)s_i10[s] * CC]);
        float2 v11 = __half22float2(*(const __half2*)&base[(size_t)s_i11[s] * CC]);
        float w0 = s_w[s][0], w1 = s_w[s][1], w2 = s_w[s][2], w3 = s_w[s][3];
        int p = s >> 2;
        acc[p].x += w0 * v00.x + w1 * v01.x + w2 * v10.x + w3 * v11.x;
        acc[p].y += w0 * v00.y + w1 * v01.y + w2 * v10.y + w3 * v11.y;
    }

    size_t o = (size_t)n * FEAT + 2 * c2;
    #pragma unroll
    for (int p = 0; p < 9; p++) {
        float vx = acc[p].x * 0.25f;
        float vy = acc[p].y * 0.25f;
        __nv_bfloat162 h = __floats2bfloat162_rn(vx, vy);
        __nv_bfloat162 l = __floats2bfloat162_rn(vx - __low2float(h),
                                                 vy - __high2float(h));
        *(unsigned*)&g_xH[o + (size_t)p * CC] = *(unsigned*)&h;
        *(unsigned*)&g_xL[o + (size_t)p * CC] = *(unsigned*)&l;
    }
}

// ---------------------------------------------------------------------------
// K1b: convert all GEMM weights to bf16 hi/lo planes
// ---------------------------------------------------------------------------
__global__ __launch_bounds__(256) void wconv_kernel(
    const float* __restrict__ w_sh1, const float* __restrict__ w_sh2,
    const float* __restrict__ w_cls1, const float* __restrict__ w_cls2,
    const float* __restrict__ w_iou1, const float* __restrict__ w_iou2,
    const float* __restrict__ w_reg1, const float* __restrict__ w_reg2)
{
    int i4 = blockIdx.x * blockDim.x + threadIdx.x;
    if (i4 >= WTOT / 4) return;
    int idx = i4 * 4;

    const float* src;
    int loc;
    if      (idx < OFF_SH2)  { src = w_sh1;  loc = idx - OFF_SH1;  }
    else if (idx < OFF_CLS1) { src = w_sh2;  loc = idx - OFF_SH2;  }
    else if (idx < OFF_CLS2) { src = w_cls1; loc = idx - OFF_CLS1; }
    else if (idx < OFF_IOU1) { src = w_cls2; loc = idx - OFF_CLS2; }
    else if (idx < OFF_IOU2) { src = w_iou1; loc = idx - OFF_IOU1; }
    else if (idx < OFF_REG1) { src = w_iou2; loc = idx - OFF_IOU2; }
    else if (idx < OFF_REG2) { src = w_reg1; loc = idx - OFF_REG1; }
    else                     { src = w_reg2; loc = idx - OFF_REG2; }

    float4 v = *(const float4*)(src + loc);
    __nv_bfloat162 h0 = __floats2bfloat162_rn(v.x, v.y);
    __nv_bfloat162 l0 = __floats2bfloat162_rn(v.x - __low2float(h0), v.y - __high2float(h0));
    __nv_bfloat162 h1 = __floats2bfloat162_rn(v.z, v.w);
    __nv_bfloat162 l1 = __floats2bfloat162_rn(v.z - __low2float(h1), v.w - __high2float(h1));
    ((uint2*)g_wH)[i4] = make_uint2(*(unsigned*)&h0, *(unsigned*)&h1);
    ((uint2*)g_wL)[i4] = make_uint2(*(unsigned*)&l0, *(unsigned*)&l1);
}

// ---------------------------------------------------------------------------
// MMA helpers
// ---------------------------------------------------------------------------
__device__ __forceinline__ void mma16(float* c, const unsigned* a, const unsigned* b) {
    asm volatile(
        "mma.sync.aligned.m16n8k16.row.col.f32.bf16.bf16.f32 "
        "{%0,%1,%2,%3}, {%4,%5,%6,%7}, {%8,%9}, {%0,%1,%2,%3};\n"
        : "+f"(c[0]), "+f"(c[1]), "+f"(c[2]), "+f"(c[3])
        : "r"(a[0]), "r"(a[1]), "r"(a[2]), "r"(a[3]), "r"(b[0]), "r"(b[1]));
}

__device__ __forceinline__ void ldsm4(unsigned& r0, unsigned& r1,
                                      unsigned& r2, unsigned& r3, unsigned addr) {
    asm volatile(
        "ldmatrix.sync.aligned.m8n8.x4.shared.b16 {%0,%1,%2,%3}, [%4];"
        : "=r"(r0), "=r"(r1), "=r"(r2), "=r"(r3) : "r"(addr));
}

#define SROW 12   // words per smem row (pitch)

// ---------------------------------------------------------------------------
// K2a: sh1 big-tile GEMM. CTA 128x128, 256 thr (8 warps of 32Mx64N), split-K.
// Dynamic smem: 2 stages x 4 planes x [128][12] words = 48 KB.
// D += aH*wH + aL*wH + aH*wL ; raw fp32 partials out.
// ---------------------------------------------------------------------------
__global__ __launch_bounds__(256) void gemm_sh1_big(
    const __nv_bfloat16* __restrict__ AH, const __nv_bfloat16* __restrict__ AL,
    int Krow, int Kchunk, float* __restrict__ Cf, size_t cZstride)
{
    extern __shared__ unsigned sm[];
    const int PW = 128 * SROW;        // words per plane (1536)
    const int SW = 4 * PW;            // words per stage

    int z = blockIdx.z;
    int kBase = z * Kchunk;
    int row0 = blockIdx.y * 128, col0 = blockIdx.x * 128;
    int tid = threadIdx.x, warp = tid >> 5, lane = tid & 31;
    int g = lane >> 2, tg = lane & 3;
    int wm = (warp >> 1) * 32, wn = (warp & 1) * 64;

    int lr = tid >> 1;                              // 0..127
    int lq = (tid & 1) * 8;
    int sbase = (lq >> 1) ^ (((lr >> 3) & 1) << 2);

    size_t abase = (size_t)(row0 + lr) * Krow + kBase + lq;
    size_t wbase = (size_t)OFF_SH1 + (size_t)(col0 + lr) * Krow + kBase + lq;

    unsigned sub = lane >> 3, rowoff = lane & 7;
    int arow = wm + ((sub & 1) << 3) + rowoff;
    int aj   = sub >> 1;
    int brow = wn + ((sub >> 1) << 3) + rowoff;
    int bj   = sub & 1;

    unsigned smBase = (unsigned)__cvta_generic_to_shared(sm);

    uint4 pa_h = *(const uint4*)(AH + abase);
    uint4 pa_l = *(const uint4*)(AL + abase);
    uint4 pw_h = *(const uint4*)(g_wH + wbase);
    uint4 pw_l = *(const uint4*)(g_wL + wbase);

    float acc[2][8][4];
    #pragma unroll
    for (int i = 0; i < 2; i++)
        #pragma unroll
        for (int j = 0; j < 8; j++)
            #pragma unroll
            for (int k = 0; k < 4; k++) acc[i][j][k] = 0.0f;

    // prologue: stage 0
    *(uint4*)(sm + 0 * SW + 0 * PW + lr * SROW + sbase) = pa_h;
    *(uint4*)(sm + 0 * SW + 1 * PW + lr * SROW + sbase) = pa_l;
    *(uint4*)(sm + 0 * SW + 2 * PW + lr * SROW + sbase) = pw_h;
    *(uint4*)(sm + 0 * SW + 3 * PW + lr * SROW + sbase) = pw_l;
    __syncthreads();

    int nIter = Kchunk / 16;
    for (int it = 0; it < nIter; it++) {
        int cur = it & 1, nxt = cur ^ 1;
        bool hasNext = (it + 1 < nIter);

        if (hasNext) {
            int ko = (it + 1) * 16;
            pa_h = *(const uint4*)(AH + abase + ko);
            pa_l = *(const uint4*)(AL + abase + ko);
            pw_h = *(const uint4*)(g_wH + wbase + ko);
            pw_l = *(const uint4*)(g_wL + wbase + ko);
        }

        unsigned stByte = (unsigned)(cur * SW * 4);
        unsigned aH[2][4], aL[2][4], bHf[8][2], bLf[8][2];
        #pragma unroll
        for (int mt = 0; mt < 2; mt++) {
            int r = arow + mt * 16;
            unsigned boff = stByte + (r * SROW + 4 * (aj ^ ((r >> 3) & 1))) * 4;
            ldsm4(aH[mt][0], aH[mt][1], aH[mt][2], aH[mt][3], smBase + boff);
            ldsm4(aL[mt][0], aL[mt][1], aL[mt][2], aL[mt][3], smBase + boff + PW * 4);
        }
        #pragma unroll
        for (int p = 0; p < 4; p++) {
            int nn = brow + p * 16;
            unsigned boff = stByte + (nn * SROW + 4 * (bj ^ ((nn >> 3) & 1))) * 4;
            ldsm4(bHf[2*p][0], bHf[2*p][1], bHf[2*p+1][0], bHf[2*p+1][1],
                  smBase + boff + 2 * PW * 4);
            ldsm4(bLf[2*p][0], bLf[2*p][1], bLf[2*p+1][0], bLf[2*p+1][1],
                  smBase + boff + 3 * PW * 4);
        }

        if (hasNext) {
            *(uint4*)(sm + nxt * SW + 0 * PW + lr * SROW + sbase) = pa_h;
            *(uint4*)(sm + nxt * SW + 1 * PW + lr * SROW + sbase) = pa_l;
            *(uint4*)(sm + nxt * SW + 2 * PW + lr * SROW + sbase) = pw_h;
            *(uint4*)(sm + nxt * SW + 3 * PW + lr * SROW + sbase) = pw_l;
        }

        #pragma unroll
        for (int mt = 0; mt < 2; mt++)
            #pragma unroll
            for (int nt = 0; nt < 8; nt++) {
                mma16(acc[mt][nt], aH[mt], bHf[nt]);
                mma16(acc[mt][nt], aL[mt], bHf[nt]);
                mma16(acc[mt][nt], aH[mt], bLf[nt]);
            }

        __syncthreads();
    }

    #pragma unroll
    for (int mt = 0; mt < 2; mt++) {
        int r = row0 + wm + mt * 16 + g;
        #pragma unroll
        for (int nt = 0; nt < 8; nt++) {
            int cb = col0 + wn + nt * 8 + 2 * tg;
            size_t i0 = cZstride * (size_t)z + (size_t)r * DD + cb;
            size_t i1 = cZstride * (size_t)z + (size_t)(r + 8) * DD + cb;
            *(float2*)&Cf[i0] = make_float2(acc[mt][nt][0], acc[mt][nt][1]);
            *(float2*)&Cf[i1] = make_float2(acc[mt][nt][2], acc[mt][nt][3]);
        }
    }
}

// ---------------------------------------------------------------------------
// K2: DD-GEMM (as R12). CTA 64x64, 128 thr, double-buffered, ldmatrix.
// ---------------------------------------------------------------------------
__global__ __launch_bounds__(128) void gemm_bf16hl_kernel(
    const __nv_bfloat16* __restrict__ AH, const __nv_bfloat16* __restrict__ AL,
    size_t aZstride, int Krow,
    size_t off0, size_t off1, size_t off2,
    float* __restrict__ Cf, unsigned* __restrict__ CH, unsigned* __restrict__ CL,
    size_t cZstride, int outMode)
{
    __shared__ unsigned AsH[2][64][SROW], AsL[2][64][SROW];
    __shared__ unsigned BsH[2][64][SROW], BsL[2][64][SROW];

    int z = blockIdx.z;
    size_t woff = (z == 0) ? off0 : (z == 1) ? off1 : off2;
    size_t aoff = aZstride * (size_t)z;

    int row0 = blockIdx.y * 64, col0 = blockIdx.x * 64;
    int tid  = threadIdx.x;
    int warp = tid >> 5, lane = tid & 31;
    int g = lane >> 2, tg = lane & 3;
    int wm = (warp >> 1) * 32, wn = (warp & 1) * 32;

    int lr = tid >> 1;
    int lq = (tid & 1) * 8;
    int sbase = (lq >> 1) ^ (((lr >> 3) & 1) << 2);

    size_t abase = aoff + (size_t)(row0 + lr) * Krow + lq;
    size_t wbase = woff + (size_t)(col0 + lr) * Krow + lq;

    unsigned sub = lane >> 3, rowoff = lane & 7;
    int arow = wm + ((sub & 1) << 3) + rowoff;
    int aj   = sub >> 1;
    int brow = wn + ((sub >> 1) << 3) + rowoff;
    int bj   = sub & 1;

    unsigned baseAH = (unsigned)__cvta_generic_to_shared(&AsH[0][0][0]);
    unsigned baseAL = (unsigned)__cvta_generic_to_shared(&AsL[0][0][0]);
    unsigned baseBH = (unsigned)__cvta_generic_to_shared(&BsH[0][0][0]);
    unsigned baseBL = (unsigned)__cvta_generic_to_shared(&BsL[0][0][0]);
    const unsigned planeBytes = 64 * SROW * 4;

    uint4 pa_h = *(const uint4*)(AH + abase);
    uint4 pa_l = *(const uint4*)(AL + abase);
    uint4 pw_h = *(const uint4*)(g_wH + wbase);
    uint4 pw_l = *(const uint4*)(g_wL + wbase);

    float acc[2][4][4];
    #pragma unroll
    for (int i = 0; i < 2; i++)
        #pragma unroll
        for (int j = 0; j < 4; j++)
            #pragma unroll
            for (int k = 0; k < 4; k++) acc[i][j][k] = 0.0f;

    *(uint4*)&AsH[0][lr][sbase] = pa_h;
    *(uint4*)&AsL[0][lr][sbase] = pa_l;
    *(uint4*)&BsH[0][lr][sbase] = pw_h;
    *(uint4*)&BsL[0][lr][sbase] = pw_l;
    __syncthreads();

    int nIter = Krow / 16;   // K == Krow for these layers (DD)
    for (int it = 0; it < nIter; it++) {
        int cur = it & 1, nxt = cur ^ 1;
        bool hasNext = (it + 1 < nIter);

        if (hasNext) {
            int ko = (it + 1) * 16;
            pa_h = *(const uint4*)(AH + abase + ko);
            pa_l = *(const uint4*)(AL + abase + ko);
            pw_h = *(const uint4*)(g_wH + wbase + ko);
            pw_l = *(const uint4*)(g_wL + wbase + ko);
        }

        unsigned aH[2][4], aL[2][4], bHf[4][2], bLf[4][2];
        unsigned curOff = cur * planeBytes;
        #pragma unroll
        for (int mt = 0; mt < 2; mt++) {
            int r = arow + mt * 16;
            unsigned boff = curOff + (r * SROW + 4 * (aj ^ ((r >> 3) & 1))) * 4;
            ldsm4(aH[mt][0], aH[mt][1], aH[mt][2], aH[mt][3], baseAH + boff);
            ldsm4(aL[mt][0], aL[mt][1], aL[mt][2], aL[mt][3], baseAL + boff);
        }
        #pragma unroll
        for (int p = 0; p < 2; p++) {
            int nn = brow + p * 16;
            unsigned boff = curOff + (nn * SROW + 4 * (bj ^ ((nn >> 3) & 1))) * 4;
            ldsm4(bHf[2*p][0], bHf[2*p][1], bHf[2*p+1][0], bHf[2*p+1][1], baseBH + boff);
            ldsm4(bLf[2*p][0], bLf[2*p][1], bLf[2*p+1][0], bLf[2*p+1][1], baseBL + boff);
        }

        if (hasNext) {
            *(uint4*)&AsH[nxt][lr][sbase] = pa_h;
            *(uint4*)&AsL[nxt][lr][sbase] = pa_l;
            *(uint4*)&BsH[nxt][lr][sbase] = pw_h;
            *(uint4*)&BsL[nxt][lr][sbase] = pw_l;
        }

        #pragma unroll
        for (int mt = 0; mt < 2; mt++)
            #pragma unroll
            for (int nt = 0; nt < 4; nt++) {
                mma16(acc[mt][nt], aH[mt], bHf[nt]);
                mma16(acc[mt][nt], aL[mt], bHf[nt]);
                mma16(acc[mt][nt], aH[mt], bLf[nt]);
            }

        __syncthreads();
    }

    #pragma unroll
    for (int mt = 0; mt < 2; mt++) {
        int r = row0 + wm + mt * 16 + g;
        #pragma unroll
        for (int nt = 0; nt < 4; nt++) {
            int cb = col0 + wn + nt * 8 + 2 * tg;
            float v0 = acc[mt][nt][0], v1 = acc[mt][nt][1];
            float v2 = acc[mt][nt][2], v3 = acc[mt][nt][3];
            v0 = fmaxf(v0, 0.0f); v1 = fmaxf(v1, 0.0f);
            v2 = fmaxf(v2, 0.0f); v3 = fmaxf(v3, 0.0f);
            size_t i0 = cZstride * (size_t)z + (size_t)r * DD + cb;
            size_t i1 = cZstride * (size_t)z + (size_t)(r + 8) * DD + cb;
            if (outMode == 2) {
                __nv_bfloat162 h0 = __floats2bfloat162_rn(v0, v1);
                __nv_bfloat162 l0 = __floats2bfloat162_rn(v0 - __low2float(h0),
                                                          v1 - __high2float(h0));
                __nv_bfloat162 h1 = __floats2bfloat162_rn(v2, v3);
                __nv_bfloat162 l1 = __floats2bfloat162_rn(v2 - __low2float(h1),
                                                          v3 - __high2float(h1));
                CH[i0 >> 1] = *(unsigned*)&h0;
                CL[i0 >> 1] = *(unsigned*)&l0;
                CH[i1 >> 1] = *(unsigned*)&h1;
                CL[i1 >> 1] = *(unsigned*)&l1;
            } else {
                *(float2*)&Cf[i0] = make_float2(v0, v1);
                *(float2*)&Cf[i1] = make_float2(v2, v3);
            }
        }
    }
}

// ---------------------------------------------------------------------------
// K2b: reduce KSPLIT1 split-K partials + relu -> bf16 hi/lo
// ---------------------------------------------------------------------------
__global__ __launch_bounds__(256) void reduceN_relu_kernel(
    const float* __restrict__ p, int n4)
{
    int i = blockIdx.x * blockDim.x + threadIdx.x;
    if (i >= n4) return;
    const float4* p4 = (const float4*)p;
    float4 s = p4[i];
    #pragma unroll
    for (int j = 1; j < KSPLIT1; j++) {
        float4 q = p4[i + (size_t)j * n4];
        s.x += q.x; s.y += q.y; s.z += q.z; s.w += q.w;
    }
    float x = fmaxf(s.x, 0.0f), y = fmaxf(s.y, 0.0f);
    float z = fmaxf(s.z, 0.0f), w = fmaxf(s.w, 0.0f);
    __nv_bfloat162 h0 = __floats2bfloat162_rn(x, y);
    __nv_bfloat162 l0 = __floats2bfloat162_rn(x - __low2float(h0), y - __high2float(h0));
    __nv_bfloat162 h1 = __floats2bfloat162_rn(z, w);
    __nv_bfloat162 l1 = __floats2bfloat162_rn(z - __low2float(h1), w - __high2float(h1));
    ((uint2*)g_aH)[i] = make_uint2(*(unsigned*)&h0, *(unsigned*)&h1);
    ((uint2*)g_aL)[i] = make_uint2(*(unsigned*)&l0, *(unsigned*)&l1);
}

// ---------------------------------------------------------------------------
// K3: all three heads in one launch. Warp per (branch, row).
// ---------------------------------------------------------------------------
__global__ __launch_bounds__(256) void head_all_kernel(
    const float* __restrict__ Abase,
    const float* __restrict__ w_cls3, const float* __restrict__ b_cls3,
    const float* __restrict__ w_iou3, const float* __restrict__ b_iou3,
    const float* __restrict__ w_reg3, const float* __restrict__ b_reg3,
    float* __restrict__ out, int N)
{
    int gw   = (int)((blockIdx.x * blockDim.x + threadIdx.x) >> 5);
    int lane = threadIdx.x & 31;
    if (gw >= 3 * N) return;
    int br = gw / N, n = gw % N;

    const float* a = Abase + (size_t)br * N * DD + (size_t)n * DD;
    float av[8];
    #pragma unroll
    for (int i = 0; i < 8; i++) av[i] = a[lane + 32 * i];

    const float* Wm = (br == 0) ? w_cls3 : (br == 1) ? w_iou3 : w_reg3;
    const float* bs = (br == 0) ? b_cls3 : (br == 1) ? b_iou3 : b_reg3;
    int Dout = (br == 2) ? 7 : 1;
    float* o = out + ((br == 0) ? n : (br == 1) ? (N + n) : (2 * N + n * 7));

    for (int d = 0; d < Dout; d++) {
        const float* w = Wm + (size_t)d * DD;
        float s = 0.0f;
        #pragma unroll
        for (int i = 0; i < 8; i++) s = fmaf(av[i], w[lane + 32 * i], s);
        #pragma unroll
        for (int off = 16; off > 0; off >>= 1)
            s += __shfl_xor_sync(0xffffffffu, s, off);
        if (lane == 0) o[d] = s + bs[d];
    }
}

// ---------------------------------------------------------------------------
extern "C" void kernel_launch(void* const* d_in, const int* in_sizes, int n_in,
                              void* d_out, int out_size) {
    const float* fm     = (const float*)d_in[0];
    const float* boxes  = (const float*)d_in[1];
    const int*   bidx   = (const int*)  d_in[2];
    const float* w_sh1  = (const float*)d_in[3];
    const float* w_sh2  = (const float*)d_in[4];
    const float* w_cls1 = (const float*)d_in[5];
    const float* w_cls2 = (const float*)d_in[6];
    const float* w_cls3 = (const float*)d_in[7];
    const float* b_cls3 = (const float*)d_in[8];
    const float* w_iou1 = (const float*)d_in[9];
    const float* w_iou2 = (const float*)d_in[10];
    const float* w_iou3 = (const float*)d_in[11];
    const float* b_iou3 = (const float*)d_in[12];
    const float* w_reg1 = (const float*)d_in[13];
    const float* w_reg2 = (const float*)d_in[14];
    const float* w_reg3 = (const float*)d_in[15];
    const float* b_reg3 = (const float*)d_in[16];

    float* out = (float*)d_out;
    int N = in_sizes[2];   // 2048

    float *part1, *bufL2;
    __nv_bfloat16 *xH, *xL, *aH, *aL, *shH, *shL, *l1H, *l1L;
    cudaGetSymbolAddress((void**)&part1, g_part1);
    cudaGetSymbolAddress((void**)&bufL2, g_bufL2);
    cudaGetSymbolAddress((void**)&xH, g_xH);
    cudaGetSymbolAddress((void**)&xL, g_xL);
    cudaGetSymbolAddress((void**)&aH, g_aH);
    cudaGetSymbolAddress((void**)&aL, g_aL);
    cudaGetSymbolAddress((void**)&shH, g_shH);
    cudaGetSymbolAddress((void**)&shL, g_shL);
    cudaGetSymbolAddress((void**)&l1H, g_l1H);
    cudaGetSymbolAddress((void**)&l1L, g_l1L);

    const int BIG_SMEM = 2 * 4 * 128 * SROW * 4;   // 49152 bytes
    cudaFuncSetAttribute(gemm_sh1_big,
                         cudaFuncAttributeMaxDynamicSharedMemorySize, BIG_SMEM);

    // 0) convert weights to bf16 hi/lo planes
    wconv_kernel<<<(WTOT / 4 + 255) / 256, 256>>>(w_sh1, w_sh2, w_cls1, w_cls2,
                                                  w_iou1, w_iou2, w_reg1, w_reg2);

    // 1) transpose+convert feature map (coalesced half2 writes)
    transpose_kernel<<<dim3(HWSZ / 32, CC / 64, BB), dim3(32, 8)>>>(fm);

    // 2) rotated ROI align (half2 gather)
    roi_kernel<<<N, 128>>>(boxes, bidx);

    size_t sND = (size_t)N * DD;
    int n4 = (int)(sND / 4);

    // 3) sh1: big-tile split-K x9 (K=2304 -> 9*256), fp32 partials, 288 CTAs
    gemm_sh1_big<<<dim3(DD / 128, N / 128, KSPLIT1), 256, BIG_SMEM>>>(
        xH, xL, FEAT, FEAT / KSPLIT1, part1, sND);

    // 3b) reduce partials + relu -> aH/aL (bf16 hi/lo)
    reduceN_relu_kernel<<<(n4 + 255) / 256, 256>>>(part1, n4);

    dim3 blk(128);

    // 4) sh2 -> shH/shL
    gemm_bf16hl_kernel<<<dim3(DD / 64, N / 64, 1), blk>>>(
        aH, aL, 0, DD,
        OFF_SH2, OFF_SH2, OFF_SH2, nullptr, (unsigned*)shH, (unsigned*)shL, 0, 2);

    // 5) branch layer 1 (batched over 3 branches) -> l1H/l1L
    gemm_bf16hl_kernel<<<dim3(DD / 64, N / 64, 3), blk>>>(
        shH, shL, 0, DD,
        OFF_CLS1, OFF_IOU1, OFF_REG1, nullptr, (unsigned*)l1H, (unsigned*)l1L, sND, 2);

    // 6) branch layer 2 (batched) -> fp32 relu bufL2
    gemm_bf16hl_kernel<<<dim3(DD / 64, N / 64, 3), blk>>>(
        l1H, l1L, sND, DD,
        OFF_CLS2, OFF_IOU2, OFF_REG2, bufL2, nullptr, nullptr, sND, 1);

    // 7) all heads in one launch
    int hblocks = (3 * N * 32 + 255) / 256;
    head_all_kernel<<<hblocks, 256>>>(bufL2, w_cls3, b_cls3, w_iou3, b_iou3,
                                      w_reg3, b_reg3, out, N);
}